// round 1
// baseline (speedup 1.0000x reference)
#include <cuda_runtime.h>
#include <cstdint>

// ---------------------------------------------------------------------------
// Problem dimensions (fixed by the reference)
// ---------------------------------------------------------------------------
#define BATCH     32
#define HEADS     12
#define SEQ       576
#define HD        64
#define CDIM      768
#define MROWS     (BATCH * SEQ)      // 18432
#define QKV_COLS  (3 * CDIM)         // 2304
#define GRID_SZ   24                 // sqrt(576)
#define MSIZE     47                 // 2*24-1
#define MASK_D    12                 // int((23+1)*0.5)
#define SOFT_SCALE 0.125f            // 64^-0.5

// ---------------------------------------------------------------------------
// Scratch (device globals; no runtime allocation allowed)
// ---------------------------------------------------------------------------
__device__ float g_qkv[(size_t)MROWS * QKV_COLS];       // 170 MB: qkv in [B*N, 3C]
__device__ float g_bm[(size_t)HEADS * SEQ * SEQ];       // 16 MB: bias+mask [H,N,N]
__device__ float g_x2[(size_t)MROWS * CDIM];            // 57 MB: attention out [B*N, C]

// ---------------------------------------------------------------------------
// f32x2 packed-math helpers (Blackwell dual-fp32 pipe; ptxas won't auto-fuse)
// ---------------------------------------------------------------------------
__device__ __forceinline__ unsigned long long splat2(float x) {
    unsigned long long r;
    asm("mov.b64 %0, {%1, %1};" : "=l"(r) : "f"(x));
    return r;
}
__device__ __forceinline__ void ffma2(unsigned long long& c,
                                      unsigned long long a,
                                      unsigned long long b) {
    asm("fma.rn.f32x2 %0, %1, %2, %3;" : "=l"(c) : "l"(a), "l"(b), "l"(c));
}
__device__ __forceinline__ void fmul2(unsigned long long& a, unsigned long long b) {
    asm("mul.rn.f32x2 %0, %1, %2;" : "=l"(a) : "l"(a), "l"(b));
}
__device__ __forceinline__ float2 unpk(unsigned long long v) {
    float2 f;
    asm("mov.b64 {%0, %1}, %2;" : "=f"(f.x), "=f"(f.y) : "l"(v));
    return f;
}

// ---------------------------------------------------------------------------
// Kernel 0: precompute bias + mask  ->  g_bm[h][q][k]
//   REL_IDX[q,k] = (kr-qr+23)*47 + (kc-qc+23)
//   mask = -100 if max(|dr|,|dc|) > 12
// ---------------------------------------------------------------------------
__global__ void biasmask_kernel(const float* __restrict__ rel_table) {
    int t = blockIdx.x * 256 + threadIdx.x;
    if (t >= HEADS * SEQ * SEQ) return;
    int h = t / (SEQ * SEQ);
    int r = t - h * (SEQ * SEQ);
    int q = r / SEQ;
    int k = r - q * SEQ;
    int qr = q / GRID_SZ, qc = q - qr * GRID_SZ;
    int kr = k / GRID_SZ, kc = k - kr * GRID_SZ;
    int dr = kr - qr, dc = kc - qc;
    int idx = (dr + GRID_SZ - 1) * MSIZE + (dc + GRID_SZ - 1);
    float v = rel_table[idx * HEADS + h];
    int cheb = max(abs(dr), abs(dc));
    if (cheb > MASK_D) v += -100.0f;
    g_bm[t] = v;
}

// ---------------------------------------------------------------------------
// Generic K=768 GEMM:  C[M,Nt] = A[M,768] @ W[768,Nt] + bias[Nt]
// 128x128 tile, BK=16, 256 threads, 8x8 per thread, f32x2 accumulators.
// All dims divisible by tile sizes (M=18432, Nt in {2304,768}) -> no bounds.
// ---------------------------------------------------------------------------
__global__ __launch_bounds__(256) void gemm_k768(
    const float* __restrict__ A, const float* __restrict__ W,
    const float* __restrict__ bias, float* __restrict__ C, int Nt)
{
    __shared__ float As[128 * 16];   // [m][k] natural
    __shared__ float Bs[16 * 128];   // [k][n] natural

    const int tid = threadIdx.x;
    const int tx = tid & 15, ty = tid >> 4;
    const int bmi = blockIdx.y, bni = blockIdx.x;

    const float* Ab = A + (size_t)bmi * 128 * CDIM;
    const float* Wb = W + (size_t)bni * 128;

    const int arow = tid >> 2;          // 0..63
    const int acol = (tid & 3) << 2;    // 0,4,8,12
    const int brow = tid >> 5;          // 0..7
    const int bcol = (tid & 31) << 2;   // 0..124

    unsigned long long cc[8][4];
#pragma unroll
    for (int i = 0; i < 8; i++)
#pragma unroll
        for (int j = 0; j < 4; j++) cc[i][j] = 0ull;

    for (int k0 = 0; k0 < CDIM; k0 += 16) {
        float4 a0 = *(const float4*)(Ab + (size_t)arow * CDIM + k0 + acol);
        float4 a1 = *(const float4*)(Ab + (size_t)(arow + 64) * CDIM + k0 + acol);
        float4 b0 = *(const float4*)(Wb + (size_t)(k0 + brow) * Nt + bcol);
        float4 b1 = *(const float4*)(Wb + (size_t)(k0 + brow + 8) * Nt + bcol);
        *(float4*)&As[arow * 16 + acol]        = a0;
        *(float4*)&As[(arow + 64) * 16 + acol] = a1;
        *(float4*)&Bs[brow * 128 + bcol]       = b0;
        *(float4*)&Bs[(brow + 8) * 128 + bcol] = b1;
        __syncthreads();

#pragma unroll
        for (int kk = 0; kk < 16; kk++) {
            const ulonglong2* bptr = (const ulonglong2*)&Bs[kk * 128 + tx * 8];
            ulonglong2 bl0 = bptr[0];
            ulonglong2 bl1 = bptr[1];
            unsigned long long bp0 = bl0.x, bp1 = bl0.y, bp2 = bl1.x, bp3 = bl1.y;
#pragma unroll
            for (int i = 0; i < 8; i++) {
                unsigned long long ap = splat2(As[(ty * 8 + i) * 16 + kk]);
                ffma2(cc[i][0], ap, bp0);
                ffma2(cc[i][1], ap, bp1);
                ffma2(cc[i][2], ap, bp2);
                ffma2(cc[i][3], ap, bp3);
            }
        }
        __syncthreads();
    }

    const int row0 = bmi * 128 + ty * 8;
    const int col0 = bni * 128 + tx * 8;
    float bb[8];
#pragma unroll
    for (int j = 0; j < 8; j++) bb[j] = bias[col0 + j];
#pragma unroll
    for (int i = 0; i < 8; i++) {
        float2 p0 = unpk(cc[i][0]), p1 = unpk(cc[i][1]);
        float2 p2 = unpk(cc[i][2]), p3 = unpk(cc[i][3]);
        float4 o0 = make_float4(p0.x + bb[0], p0.y + bb[1], p1.x + bb[2], p1.y + bb[3]);
        float4 o1 = make_float4(p2.x + bb[4], p2.y + bb[5], p3.x + bb[6], p3.y + bb[7]);
        float* crow = C + (size_t)(row0 + i) * Nt + col0;
        *(float4*)(crow)     = o0;
        *(float4*)(crow + 4) = o1;
    }
}

// ---------------------------------------------------------------------------
// Kernel 2: flash attention, one block per (b, h, 64-row q-tile).
// Q/K stored transposed+XOR-swizzled in smem (conflict-free LDS.128),
// scores at stride 65 (conflict-free row-parallel softmax), V natural.
// ---------------------------------------------------------------------------
#define AT_SMEM_FLOATS (4096 + 4096 + 64 * 65 + 64 + 64 + 64 + 256)
#define AT_SMEM_BYTES  (AT_SMEM_FLOATS * 4)

__global__ __launch_bounds__(256) void attn_kernel() {
    extern __shared__ float sm[];
    float* sQ  = sm;               // 4096: swizzled (d, q)
    float* sKV = sm + 4096;        // 4096: K swizzled (d,k) -> then V natural [k][d]
    float* sS  = sm + 8192;        // 64 * 65 scores / probs
    float* m_s = sm + 8192 + 64 * 65;
    float* l_s = m_s + 64;
    float* rsc = l_s + 64;
    float* red = rsc + 64;         // 4 x 64 reduction partials

    const int tid = threadIdx.x;
    const int tx = tid & 15, ty = tid >> 4;
    const int qt = blockIdx.x, h = blockIdx.y, b = blockIdx.z;
    const int q0 = qt * 64;

    const float* qkvBase = g_qkv + (size_t)b * SEQ * QKV_COLS;
    const int hoff = h * HD;

    // ---- Load Q tile, transposed + swizzled: phys = d*64 + ((q>>2)^(d>>2&15))*4 + (q&3)
    {
        const int d0 = tx << 2;
#pragma unroll
        for (int p = 0; p < 4; p++) {
            int n = p * 16 + ty;
            float4 v = *(const float4*)(qkvBase + (size_t)(q0 + n) * QKV_COLS + hoff + d0);
            int gr = (n >> 2) ^ tx;       // d0>>2 == tx
            int base = gr * 4 + (n & 3);
            sQ[(d0 + 0) * 64 + base] = v.x;
            sQ[(d0 + 1) * 64 + base] = v.y;
            sQ[(d0 + 2) * 64 + base] = v.z;
            sQ[(d0 + 3) * 64 + base] = v.w;
        }
    }
    if (tid < 64) { m_s[tid] = -1e30f; l_s[tid] = 0.0f; }

    unsigned long long accO[4][2];
#pragma unroll
    for (int i = 0; i < 4; i++) { accO[i][0] = 0ull; accO[i][1] = 0ull; }

    for (int kt = 0; kt < SEQ / 64; kt++) {
        const int k0 = kt * 64;
        __syncthreads();   // previous P@V done (and Q stores on first iter)

        // ---- Load K tile (transposed + swizzled) into sKV
        {
            const int d0 = tx << 2;
#pragma unroll
            for (int p = 0; p < 4; p++) {
                int n = p * 16 + ty;
                float4 v = *(const float4*)(qkvBase + (size_t)(k0 + n) * QKV_COLS + CDIM + hoff + d0);
                int gr = (n >> 2) ^ tx;
                int base = gr * 4 + (n & 3);
                sKV[(d0 + 0) * 64 + base] = v.x;
                sKV[(d0 + 1) * 64 + base] = v.y;
                sKV[(d0 + 2) * 64 + base] = v.z;
                sKV[(d0 + 3) * 64 + base] = v.w;
            }
        }
        __syncthreads();

        // ---- S = Q @ K^T  (4x4 per thread, f32x2)
        unsigned long long accS[4][2];
#pragma unroll
        for (int i = 0; i < 4; i++) { accS[i][0] = 0ull; accS[i][1] = 0ull; }
#pragma unroll 8
        for (int d = 0; d < 64; d++) {
            int sw = (d >> 2) & 15;
            float4 a = *(const float4*)&sQ[d * 64 + ((ty ^ sw) << 2)];
            ulonglong2 bv = *(const ulonglong2*)&sKV[d * 64 + ((tx ^ sw) << 2)];
            unsigned long long a0 = splat2(a.x), a1 = splat2(a.y),
                               a2 = splat2(a.z), a3 = splat2(a.w);
            ffma2(accS[0][0], a0, bv.x); ffma2(accS[0][1], a0, bv.y);
            ffma2(accS[1][0], a1, bv.x); ffma2(accS[1][1], a1, bv.y);
            ffma2(accS[2][0], a2, bv.x); ffma2(accS[2][1], a2, bv.y);
            ffma2(accS[3][0], a3, bv.x); ffma2(accS[3][1], a3, bv.y);
        }

        // ---- scale + bias + mask, write score tile (stride 65)
        {
            const float* bmrow = g_bm + ((size_t)h * SEQ + (q0 + ty * 4)) * SEQ + k0 + tx * 4;
#pragma unroll
            for (int i = 0; i < 4; i++) {
                float2 s0 = unpk(accS[i][0]);
                float2 s1 = unpk(accS[i][1]);
                const float* bmp = bmrow + (size_t)i * SEQ;
                float* srow = &sS[(ty * 4 + i) * 65 + tx * 4];
                srow[0] = fmaf(s0.x, SOFT_SCALE, bmp[0]);
                srow[1] = fmaf(s0.y, SOFT_SCALE, bmp[1]);
                srow[2] = fmaf(s1.x, SOFT_SCALE, bmp[2]);
                srow[3] = fmaf(s1.y, SOFT_SCALE, bmp[3]);
            }
        }
        __syncthreads();   // S complete; K fully consumed

        // ---- Load V tile (natural [k][d]) into sKV, overwriting K
        {
            const int d0 = tx << 2;
#pragma unroll
            for (int p = 0; p < 4; p++) {
                int n = p * 16 + ty;
                float4 v = *(const float4*)(qkvBase + (size_t)(k0 + n) * QKV_COLS + 2 * CDIM + hoff + d0);
                *(float4*)&sKV[n * 64 + d0] = v;
            }
        }
        // ---- partial row max (4 threads per row, conflict-free at stride 65)
        {
            int r = tid & 63, seg = tid >> 6;
            const float* srow = &sS[r * 65 + seg * 16];
            float pm = srow[0];
#pragma unroll
            for (int j = 1; j < 16; j++) pm = fmaxf(pm, srow[j]);
            red[seg * 64 + r] = pm;
        }
        __syncthreads();
        if (tid < 64) {
            int r = tid;
            float mn = fmaxf(fmaxf(red[r], red[64 + r]), fmaxf(red[128 + r], red[192 + r]));
            float mo = m_s[r];
            mn = fmaxf(mo, mn);
            m_s[r] = mn;
            rsc[r] = __expf(mo - mn);
        }
        __syncthreads();
        // ---- exp pass + partial sums
        {
            int r = tid & 63, seg = tid >> 6;
            float mr = m_s[r];
            float* srow = &sS[r * 65 + seg * 16];
            float ps = 0.0f;
#pragma unroll
            for (int j = 0; j < 16; j++) {
                float e = __expf(srow[j] - mr);
                srow[j] = e;
                ps += e;
            }
            red[seg * 64 + r] = ps;
        }
        __syncthreads();
        if (tid < 64) {
            int r = tid;
            l_s[r] = l_s[r] * rsc[r] + (red[r] + red[64 + r]) + (red[128 + r] + red[192 + r]);
        }

        // ---- rescale O, then O += P @ V
#pragma unroll
        for (int i = 0; i < 4; i++) {
            unsigned long long sc2 = splat2(rsc[ty * 4 + i]);
            fmul2(accO[i][0], sc2);
            fmul2(accO[i][1], sc2);
        }
#pragma unroll 8
        for (int k = 0; k < 64; k++) {
            ulonglong2 vv = *(const ulonglong2*)&sKV[k * 64 + tx * 4];
            unsigned long long p0 = splat2(sS[(ty * 4 + 0) * 65 + k]);
            unsigned long long p1 = splat2(sS[(ty * 4 + 1) * 65 + k]);
            unsigned long long p2 = splat2(sS[(ty * 4 + 2) * 65 + k]);
            unsigned long long p3 = splat2(sS[(ty * 4 + 3) * 65 + k]);
            ffma2(accO[0][0], p0, vv.x); ffma2(accO[0][1], p0, vv.y);
            ffma2(accO[1][0], p1, vv.x); ffma2(accO[1][1], p1, vv.y);
            ffma2(accO[2][0], p2, vv.x); ffma2(accO[2][1], p2, vv.y);
            ffma2(accO[3][0], p3, vv.x); ffma2(accO[3][1], p3, vv.y);
        }
    }
    __syncthreads();   // l_s final

    // ---- normalize + store to g_x2 [B,N,C]
#pragma unroll
    for (int i = 0; i < 4; i++) {
        float inv = 1.0f / l_s[ty * 4 + i];
        float2 o0 = unpk(accO[i][0]);
        float2 o1 = unpk(accO[i][1]);
        float4 out = make_float4(o0.x * inv, o0.y * inv, o1.x * inv, o1.y * inv);
        *(float4*)(g_x2 + (size_t)(b * SEQ + q0 + ty * 4 + i) * CDIM + hoff + tx * 4) = out;
    }
}

// ---------------------------------------------------------------------------
// Launch
// ---------------------------------------------------------------------------
extern "C" void kernel_launch(void* const* d_in, const int* in_sizes, int n_in,
                              void* d_out, int out_size) {
    const float* x         = (const float*)d_in[0];
    const float* w_qkv     = (const float*)d_in[1];
    const float* b_qkv     = (const float*)d_in[2];
    const float* rel_table = (const float*)d_in[3];
    const float* w_proj    = (const float*)d_in[4];
    const float* b_proj    = (const float*)d_in[5];
    float* out = (float*)d_out;

    float *pqkv, *px2;
    cudaGetSymbolAddress((void**)&pqkv, g_qkv);
    cudaGetSymbolAddress((void**)&px2, g_x2);

    cudaFuncSetAttribute(attn_kernel, cudaFuncAttributeMaxDynamicSharedMemorySize,
                         AT_SMEM_BYTES);

    // 1) QKV projection: [18432,768] @ [768,2304]
    gemm_k768<<<dim3(QKV_COLS / 128, MROWS / 128), 256>>>(x, w_qkv, b_qkv, pqkv, QKV_COLS);

    // 2) bias + mask precompute (independent of kernel 1; same stream is fine)
    biasmask_kernel<<<(HEADS * SEQ * SEQ + 255) / 256, 256>>>(rel_table);

    // 3) attention
    attn_kernel<<<dim3(SEQ / 64, HEADS, BATCH), 256, AT_SMEM_BYTES>>>();

    // 4) output projection: [18432,768] @ [768,768]
    gemm_k768<<<dim3(CDIM / 128, MROWS / 128), 256>>>(px2, w_proj, b_proj, out, CDIM);
}

// round 2
// speedup vs baseline: 1.0008x; 1.0008x over previous
#include <cuda_runtime.h>
#include <cstdint>

// ---------------------------------------------------------------------------
// Problem dimensions (fixed by the reference)
// ---------------------------------------------------------------------------
#define BATCH     32
#define HEADS     12
#define SEQ       576
#define HD        64
#define CDIM      768
#define MROWS     (BATCH * SEQ)      // 18432
#define QKV_COLS  (3 * CDIM)         // 2304
#define GRID_SZ   24                 // sqrt(576)
#define MSIZE     47                 // 2*24-1
#define MASK_D    12                 // int((23+1)*0.5)
#define SOFT_SCALE 0.125f            // 64^-0.5

// ---------------------------------------------------------------------------
// Scratch (device globals; no runtime allocation allowed)
// ---------------------------------------------------------------------------
__device__ float g_qkv[(size_t)MROWS * QKV_COLS];       // 170 MB: qkv in [B*N, 3C]
__device__ float g_bm[(size_t)HEADS * SEQ * SEQ];       // 16 MB: bias+mask [H,N,N]
__device__ float g_x2[(size_t)MROWS * CDIM];            // 57 MB: attention out [B*N, C]

// ---------------------------------------------------------------------------
// f32x2 packed-math helpers (Blackwell dual-fp32 pipe; ptxas won't auto-fuse)
// ---------------------------------------------------------------------------
__device__ __forceinline__ unsigned long long splat2(float x) {
    unsigned long long r;
    asm("mov.b64 %0, {%1, %1};" : "=l"(r) : "f"(x));
    return r;
}
__device__ __forceinline__ void ffma2(unsigned long long& c,
                                      unsigned long long a,
                                      unsigned long long b) {
    asm("fma.rn.f32x2 %0, %1, %2, %3;" : "=l"(c) : "l"(a), "l"(b), "l"(c));
}
__device__ __forceinline__ void fmul2(unsigned long long& a, unsigned long long b) {
    asm("mul.rn.f32x2 %0, %1, %2;" : "=l"(a) : "l"(a), "l"(b));
}
__device__ __forceinline__ float2 unpk(unsigned long long v) {
    float2 f;
    asm("mov.b64 {%0, %1}, %2;" : "=f"(f.x), "=f"(f.y) : "l"(v));
    return f;
}

// ---------------------------------------------------------------------------
// Kernel 0: precompute bias + mask  ->  g_bm[h][q][k]
//   REL_IDX[q,k] = (kr-qr+23)*47 + (kc-qc+23)
//   mask = -100 if max(|dr|,|dc|) > 12
// ---------------------------------------------------------------------------
__global__ void biasmask_kernel(const float* __restrict__ rel_table) {
    int t = blockIdx.x * 256 + threadIdx.x;
    if (t >= HEADS * SEQ * SEQ) return;
    int h = t / (SEQ * SEQ);
    int r = t - h * (SEQ * SEQ);
    int q = r / SEQ;
    int k = r - q * SEQ;
    int qr = q / GRID_SZ, qc = q - qr * GRID_SZ;
    int kr = k / GRID_SZ, kc = k - kr * GRID_SZ;
    int dr = kr - qr, dc = kc - qc;
    int idx = (dr + GRID_SZ - 1) * MSIZE + (dc + GRID_SZ - 1);
    float v = rel_table[idx * HEADS + h];
    int cheb = max(abs(dr), abs(dc));
    if (cheb > MASK_D) v += -100.0f;
    g_bm[t] = v;
}

// ---------------------------------------------------------------------------
// Generic K=768 GEMM:  C[M,Nt] = A[M,768] @ W[768,Nt] + bias[Nt]
// 128x128 tile, BK=16, 256 threads, 8x8 per thread, f32x2 accumulators.
// All dims divisible by tile sizes (M=18432, Nt in {2304,768}) -> no bounds.
// ---------------------------------------------------------------------------
__global__ __launch_bounds__(256) void gemm_k768(
    const float* __restrict__ A, const float* __restrict__ W,
    const float* __restrict__ bias, float* __restrict__ C, int Nt)
{
    __shared__ float As[128 * 16];   // [m][k] natural
    __shared__ float Bs[16 * 128];   // [k][n] natural

    const int tid = threadIdx.x;
    const int tx = tid & 15, ty = tid >> 4;
    const int bmi = blockIdx.y, bni = blockIdx.x;

    const float* Ab = A + (size_t)bmi * 128 * CDIM;
    const float* Wb = W + (size_t)bni * 128;

    const int arow = tid >> 2;          // 0..63
    const int acol = (tid & 3) << 2;    // 0,4,8,12
    const int brow = tid >> 5;          // 0..7
    const int bcol = (tid & 31) << 2;   // 0..124

    unsigned long long cc[8][4];
#pragma unroll
    for (int i = 0; i < 8; i++)
#pragma unroll
        for (int j = 0; j < 4; j++) cc[i][j] = 0ull;

    for (int k0 = 0; k0 < CDIM; k0 += 16) {
        float4 a0 = *(const float4*)(Ab + (size_t)arow * CDIM + k0 + acol);
        float4 a1 = *(const float4*)(Ab + (size_t)(arow + 64) * CDIM + k0 + acol);
        float4 b0 = *(const float4*)(Wb + (size_t)(k0 + brow) * Nt + bcol);
        float4 b1 = *(const float4*)(Wb + (size_t)(k0 + brow + 8) * Nt + bcol);
        *(float4*)&As[arow * 16 + acol]        = a0;
        *(float4*)&As[(arow + 64) * 16 + acol] = a1;
        *(float4*)&Bs[brow * 128 + bcol]       = b0;
        *(float4*)&Bs[(brow + 8) * 128 + bcol] = b1;
        __syncthreads();

#pragma unroll
        for (int kk = 0; kk < 16; kk++) {
            const ulonglong2* bptr = (const ulonglong2*)&Bs[kk * 128 + tx * 8];
            ulonglong2 bl0 = bptr[0];
            ulonglong2 bl1 = bptr[1];
            unsigned long long bp0 = bl0.x, bp1 = bl0.y, bp2 = bl1.x, bp3 = bl1.y;
#pragma unroll
            for (int i = 0; i < 8; i++) {
                unsigned long long ap = splat2(As[(ty * 8 + i) * 16 + kk]);
                ffma2(cc[i][0], ap, bp0);
                ffma2(cc[i][1], ap, bp1);
                ffma2(cc[i][2], ap, bp2);
                ffma2(cc[i][3], ap, bp3);
            }
        }
        __syncthreads();
    }

    const int row0 = bmi * 128 + ty * 8;
    const int col0 = bni * 128 + tx * 8;
    float bb[8];
#pragma unroll
    for (int j = 0; j < 8; j++) bb[j] = bias[col0 + j];
#pragma unroll
    for (int i = 0; i < 8; i++) {
        float2 p0 = unpk(cc[i][0]), p1 = unpk(cc[i][1]);
        float2 p2 = unpk(cc[i][2]), p3 = unpk(cc[i][3]);
        float4 o0 = make_float4(p0.x + bb[0], p0.y + bb[1], p1.x + bb[2], p1.y + bb[3]);
        float4 o1 = make_float4(p2.x + bb[4], p2.y + bb[5], p3.x + bb[6], p3.y + bb[7]);
        float* crow = C + (size_t)(row0 + i) * Nt + col0;
        *(float4*)(crow)     = o0;
        *(float4*)(crow + 4) = o1;
    }
}

// ---------------------------------------------------------------------------
// Kernel 2: flash attention, one block per (b, h, 64-row q-tile).
// Q/K stored transposed+XOR-swizzled in smem (conflict-free LDS.128),
// scores at stride 65 (conflict-free row-parallel softmax), V natural.
// ---------------------------------------------------------------------------
#define AT_SMEM_FLOATS (4096 + 4096 + 64 * 65 + 64 + 64 + 64 + 256)
#define AT_SMEM_BYTES  (AT_SMEM_FLOATS * 4)

__global__ __launch_bounds__(256) void attn_kernel() {
    extern __shared__ float sm[];
    float* sQ  = sm;               // 4096: swizzled (d, q)
    float* sKV = sm + 4096;        // 4096: K swizzled (d,k) -> then V natural [k][d]
    float* sS  = sm + 8192;        // 64 * 65 scores / probs
    float* m_s = sm + 8192 + 64 * 65;
    float* l_s = m_s + 64;
    float* rsc = l_s + 64;
    float* red = rsc + 64;         // 4 x 64 reduction partials

    const int tid = threadIdx.x;
    const int tx = tid & 15, ty = tid >> 4;
    const int qt = blockIdx.x, h = blockIdx.y, b = blockIdx.z;
    const int q0 = qt * 64;

    const float* qkvBase = g_qkv + (size_t)b * SEQ * QKV_COLS;
    const int hoff = h * HD;

    // ---- Load Q tile, transposed + swizzled: phys = d*64 + ((q>>2)^(d>>2&15))*4 + (q&3)
    {
        const int d0 = tx << 2;
#pragma unroll
        for (int p = 0; p < 4; p++) {
            int n = p * 16 + ty;
            float4 v = *(const float4*)(qkvBase + (size_t)(q0 + n) * QKV_COLS + hoff + d0);
            int gr = (n >> 2) ^ tx;       // d0>>2 == tx
            int base = gr * 4 + (n & 3);
            sQ[(d0 + 0) * 64 + base] = v.x;
            sQ[(d0 + 1) * 64 + base] = v.y;
            sQ[(d0 + 2) * 64 + base] = v.z;
            sQ[(d0 + 3) * 64 + base] = v.w;
        }
    }
    if (tid < 64) { m_s[tid] = -1e30f; l_s[tid] = 0.0f; }

    unsigned long long accO[4][2];
#pragma unroll
    for (int i = 0; i < 4; i++) { accO[i][0] = 0ull; accO[i][1] = 0ull; }

    for (int kt = 0; kt < SEQ / 64; kt++) {
        const int k0 = kt * 64;
        __syncthreads();   // previous P@V done (and Q stores on first iter)

        // ---- Load K tile (transposed + swizzled) into sKV
        {
            const int d0 = tx << 2;
#pragma unroll
            for (int p = 0; p < 4; p++) {
                int n = p * 16 + ty;
                float4 v = *(const float4*)(qkvBase + (size_t)(k0 + n) * QKV_COLS + CDIM + hoff + d0);
                int gr = (n >> 2) ^ tx;
                int base = gr * 4 + (n & 3);
                sKV[(d0 + 0) * 64 + base] = v.x;
                sKV[(d0 + 1) * 64 + base] = v.y;
                sKV[(d0 + 2) * 64 + base] = v.z;
                sKV[(d0 + 3) * 64 + base] = v.w;
            }
        }
        __syncthreads();

        // ---- S = Q @ K^T  (4x4 per thread, f32x2)
        unsigned long long accS[4][2];
#pragma unroll
        for (int i = 0; i < 4; i++) { accS[i][0] = 0ull; accS[i][1] = 0ull; }
#pragma unroll 8
        for (int d = 0; d < 64; d++) {
            int sw = (d >> 2) & 15;
            float4 a = *(const float4*)&sQ[d * 64 + ((ty ^ sw) << 2)];
            ulonglong2 bv = *(const ulonglong2*)&sKV[d * 64 + ((tx ^ sw) << 2)];
            unsigned long long a0 = splat2(a.x), a1 = splat2(a.y),
                               a2 = splat2(a.z), a3 = splat2(a.w);
            ffma2(accS[0][0], a0, bv.x); ffma2(accS[0][1], a0, bv.y);
            ffma2(accS[1][0], a1, bv.x); ffma2(accS[1][1], a1, bv.y);
            ffma2(accS[2][0], a2, bv.x); ffma2(accS[2][1], a2, bv.y);
            ffma2(accS[3][0], a3, bv.x); ffma2(accS[3][1], a3, bv.y);
        }

        // ---- scale + bias + mask, write score tile (stride 65)
        {
            const float* bmrow = g_bm + ((size_t)h * SEQ + (q0 + ty * 4)) * SEQ + k0 + tx * 4;
#pragma unroll
            for (int i = 0; i < 4; i++) {
                float2 s0 = unpk(accS[i][0]);
                float2 s1 = unpk(accS[i][1]);
                const float* bmp = bmrow + (size_t)i * SEQ;
                float* srow = &sS[(ty * 4 + i) * 65 + tx * 4];
                srow[0] = fmaf(s0.x, SOFT_SCALE, bmp[0]);
                srow[1] = fmaf(s0.y, SOFT_SCALE, bmp[1]);
                srow[2] = fmaf(s1.x, SOFT_SCALE, bmp[2]);
                srow[3] = fmaf(s1.y, SOFT_SCALE, bmp[3]);
            }
        }
        __syncthreads();   // S complete; K fully consumed

        // ---- Load V tile (natural [k][d]) into sKV, overwriting K
        {
            const int d0 = tx << 2;
#pragma unroll
            for (int p = 0; p < 4; p++) {
                int n = p * 16 + ty;
                float4 v = *(const float4*)(qkvBase + (size_t)(k0 + n) * QKV_COLS + 2 * CDIM + hoff + d0);
                *(float4*)&sKV[n * 64 + d0] = v;
            }
        }
        // ---- partial row max (4 threads per row, conflict-free at stride 65)
        {
            int r = tid & 63, seg = tid >> 6;
            const float* srow = &sS[r * 65 + seg * 16];
            float pm = srow[0];
#pragma unroll
            for (int j = 1; j < 16; j++) pm = fmaxf(pm, srow[j]);
            red[seg * 64 + r] = pm;
        }
        __syncthreads();
        if (tid < 64) {
            int r = tid;
            float mn = fmaxf(fmaxf(red[r], red[64 + r]), fmaxf(red[128 + r], red[192 + r]));
            float mo = m_s[r];
            mn = fmaxf(mo, mn);
            m_s[r] = mn;
            rsc[r] = __expf(mo - mn);
        }
        __syncthreads();
        // ---- exp pass + partial sums
        {
            int r = tid & 63, seg = tid >> 6;
            float mr = m_s[r];
            float* srow = &sS[r * 65 + seg * 16];
            float ps = 0.0f;
#pragma unroll
            for (int j = 0; j < 16; j++) {
                float e = __expf(srow[j] - mr);
                srow[j] = e;
                ps += e;
            }
            red[seg * 64 + r] = ps;
        }
        __syncthreads();
        if (tid < 64) {
            int r = tid;
            l_s[r] = l_s[r] * rsc[r] + (red[r] + red[64 + r]) + (red[128 + r] + red[192 + r]);
        }

        // ---- rescale O, then O += P @ V
#pragma unroll
        for (int i = 0; i < 4; i++) {
            unsigned long long sc2 = splat2(rsc[ty * 4 + i]);
            fmul2(accO[i][0], sc2);
            fmul2(accO[i][1], sc2);
        }
#pragma unroll 8
        for (int k = 0; k < 64; k++) {
            ulonglong2 vv = *(const ulonglong2*)&sKV[k * 64 + tx * 4];
            unsigned long long p0 = splat2(sS[(ty * 4 + 0) * 65 + k]);
            unsigned long long p1 = splat2(sS[(ty * 4 + 1) * 65 + k]);
            unsigned long long p2 = splat2(sS[(ty * 4 + 2) * 65 + k]);
            unsigned long long p3 = splat2(sS[(ty * 4 + 3) * 65 + k]);
            ffma2(accO[0][0], p0, vv.x); ffma2(accO[0][1], p0, vv.y);
            ffma2(accO[1][0], p1, vv.x); ffma2(accO[1][1], p1, vv.y);
            ffma2(accO[2][0], p2, vv.x); ffma2(accO[2][1], p2, vv.y);
            ffma2(accO[3][0], p3, vv.x); ffma2(accO[3][1], p3, vv.y);
        }
    }
    __syncthreads();   // l_s final

    // ---- normalize + store to g_x2 [B,N,C]
#pragma unroll
    for (int i = 0; i < 4; i++) {
        float inv = 1.0f / l_s[ty * 4 + i];
        float2 o0 = unpk(accO[i][0]);
        float2 o1 = unpk(accO[i][1]);
        float4 out = make_float4(o0.x * inv, o0.y * inv, o1.x * inv, o1.y * inv);
        *(float4*)(g_x2 + (size_t)(b * SEQ + q0 + ty * 4 + i) * CDIM + hoff + tx * 4) = out;
    }
}

// ---------------------------------------------------------------------------
// Launch
// ---------------------------------------------------------------------------
extern "C" void kernel_launch(void* const* d_in, const int* in_sizes, int n_in,
                              void* d_out, int out_size) {
    const float* x         = (const float*)d_in[0];
    const float* w_qkv     = (const float*)d_in[1];
    const float* b_qkv     = (const float*)d_in[2];
    const float* rel_table = (const float*)d_in[3];
    const float* w_proj    = (const float*)d_in[4];
    const float* b_proj    = (const float*)d_in[5];
    float* out = (float*)d_out;

    float *pqkv, *px2;
    cudaGetSymbolAddress((void**)&pqkv, g_qkv);
    cudaGetSymbolAddress((void**)&px2, g_x2);

    cudaFuncSetAttribute(attn_kernel, cudaFuncAttributeMaxDynamicSharedMemorySize,
                         AT_SMEM_BYTES);

    // 1) QKV projection: [18432,768] @ [768,2304]
    gemm_k768<<<dim3(QKV_COLS / 128, MROWS / 128), 256>>>(x, w_qkv, b_qkv, pqkv, QKV_COLS);

    // 2) bias + mask precompute (independent of kernel 1; same stream is fine)
    biasmask_kernel<<<(HEADS * SEQ * SEQ + 255) / 256, 256>>>(rel_table);

    // 3) attention
    attn_kernel<<<dim3(SEQ / 64, HEADS, BATCH), 256, AT_SMEM_BYTES>>>();

    // 4) output projection: [18432,768] @ [768,768]
    gemm_k768<<<dim3(CDIM / 128, MROWS / 128), 256>>>(px2, w_proj, b_proj, out, CDIM);
}

// round 5
// speedup vs baseline: 1.8276x; 1.8262x over previous
#include <cuda_runtime.h>
#include <cuda_bf16.h>
#include <cstdint>

// ---------------------------------------------------------------------------
// Problem dimensions (fixed by the reference)
// ---------------------------------------------------------------------------
#define BATCH     32
#define HEADS     12
#define SEQ       576
#define HD        64
#define CDIM      768
#define MROWS     (BATCH * SEQ)      // 18432
#define QKV_COLS  (3 * CDIM)         // 2304
#define GRID_SZ   24                 // sqrt(576)
#define MSIZE     47                 // 2*24-1
#define MASK_D    12                 // int((23+1)*0.5)
#define SOFT_SCALE 0.125f            // 64^-0.5

// ---------------------------------------------------------------------------
// Scratch (device globals; no runtime allocation allowed)
// ---------------------------------------------------------------------------
__device__ float g_qkv[(size_t)MROWS * QKV_COLS];       // 170 MB
__device__ float g_bm[(size_t)HEADS * SEQ * SEQ];       // 16 MB
__device__ float g_x2[(size_t)MROWS * CDIM];            // 57 MB

// bf16 hi/lo split operands
__device__ __nv_bfloat16 g_xh[(size_t)MROWS * CDIM];    // 28 MB
__device__ __nv_bfloat16 g_xl[(size_t)MROWS * CDIM];
__device__ __nv_bfloat16 g_x2h[(size_t)MROWS * CDIM];
__device__ __nv_bfloat16 g_x2l[(size_t)MROWS * CDIM];
__device__ __nv_bfloat16 g_wqkvTh[(size_t)QKV_COLS * CDIM];
__device__ __nv_bfloat16 g_wqkvTl[(size_t)QKV_COLS * CDIM];
__device__ __nv_bfloat16 g_wprojTh[(size_t)CDIM * CDIM];
__device__ __nv_bfloat16 g_wprojTl[(size_t)CDIM * CDIM];

// ---------------------------------------------------------------------------
// f32x2 packed-math helpers (fp32 attention kernel)
// ---------------------------------------------------------------------------
__device__ __forceinline__ unsigned long long splat2(float x) {
    unsigned long long r;
    asm("mov.b64 %0, {%1, %1};" : "=l"(r) : "f"(x));
    return r;
}
__device__ __forceinline__ void ffma2(unsigned long long& c,
                                      unsigned long long a,
                                      unsigned long long b) {
    asm("fma.rn.f32x2 %0, %1, %2, %3;" : "=l"(c) : "l"(a), "l"(b), "l"(c));
}
__device__ __forceinline__ void fmul2(unsigned long long& a, unsigned long long b) {
    asm("mul.rn.f32x2 %0, %1, %2;" : "=l"(a) : "l"(a), "l"(b));
}
__device__ __forceinline__ float2 unpk(unsigned long long v) {
    float2 f;
    asm("mov.b64 {%0, %1}, %2;" : "=f"(f.x), "=f"(f.y) : "l"(v));
    return f;
}

// ---------------------------------------------------------------------------
// cp.async helpers
// ---------------------------------------------------------------------------
__device__ __forceinline__ void cp_async16(uint32_t smem_dst, const void* gptr) {
    asm volatile("cp.async.cg.shared.global [%0], [%1], 16;"
                 :: "r"(smem_dst), "l"(gptr));
}
__device__ __forceinline__ void cp_commit() {
    asm volatile("cp.async.commit_group;");
}
__device__ __forceinline__ void cp_wait0() {
    asm volatile("cp.async.wait_group 0;");
}

// ---------------------------------------------------------------------------
// mma.sync m16n8k16 bf16 (HMMA; compute_100-legal)
// ---------------------------------------------------------------------------
__device__ __forceinline__ void mma_bf16(
    float* c, uint32_t a0, uint32_t a1, uint32_t a2, uint32_t a3,
    uint32_t b0, uint32_t b1)
{
    asm volatile(
        "mma.sync.aligned.m16n8k16.row.col.f32.bf16.bf16.f32 "
        "{%0,%1,%2,%3}, {%4,%5,%6,%7}, {%8,%9}, {%0,%1,%2,%3};"
        : "+f"(c[0]), "+f"(c[1]), "+f"(c[2]), "+f"(c[3])
        : "r"(a0), "r"(a1), "r"(a2), "r"(a3), "r"(b0), "r"(b1));
}

// hi/lo split of a float into two bf16
__device__ __forceinline__ void split_bf16(float v, __nv_bfloat16& h, __nv_bfloat16& l) {
    h = __float2bfloat16(v);
    l = __float2bfloat16(v - __bfloat162float(h));
}

// ---------------------------------------------------------------------------
// Kernel: elementwise split fp32 -> bf16 hi/lo
// ---------------------------------------------------------------------------
__global__ void split_kernel(const float* __restrict__ in,
                             __nv_bfloat16* __restrict__ hi,
                             __nv_bfloat16* __restrict__ lo, int n4) {
    int t = blockIdx.x * 256 + threadIdx.x;
    if (t >= n4) return;
    float4 v = *(const float4*)(in + (size_t)t * 4);
    __nv_bfloat16 h[4], l[4];
    split_bf16(v.x, h[0], l[0]);
    split_bf16(v.y, h[1], l[1]);
    split_bf16(v.z, h[2], l[2]);
    split_bf16(v.w, h[3], l[3]);
    *(ushort4*)(hi + (size_t)t * 4) = *(ushort4*)h;
    *(ushort4*)(lo + (size_t)t * 4) = *(ushort4*)l;
}

// ---------------------------------------------------------------------------
// Kernel: weight transpose src[R][C] -> dstH/dstL[C][R] (bf16 hi/lo)
// ---------------------------------------------------------------------------
__global__ void transpose_split_kernel(const float* __restrict__ src,
                                       __nv_bfloat16* __restrict__ dstH,
                                       __nv_bfloat16* __restrict__ dstL,
                                       int R, int C) {
    __shared__ float t[32][33];
    int bx = blockIdx.x * 32, by = blockIdx.y * 32;
#pragma unroll
    for (int i = 0; i < 32; i += 8)
        t[threadIdx.y + i][threadIdx.x] =
            src[(size_t)(by + threadIdx.y + i) * C + bx + threadIdx.x];
    __syncthreads();
#pragma unroll
    for (int i = 0; i < 32; i += 8) {
        float v = t[threadIdx.x][threadIdx.y + i];
        __nv_bfloat16 h, l;
        split_bf16(v, h, l);
        size_t o = (size_t)(bx + threadIdx.y + i) * R + by + threadIdx.x;
        dstH[o] = h;
        dstL[o] = l;
    }
}

// ---------------------------------------------------------------------------
// Kernel: precompute bias + mask  ->  g_bm[h][q][k]
// ---------------------------------------------------------------------------
__global__ void biasmask_kernel(const float* __restrict__ rel_table) {
    int t = blockIdx.x * 256 + threadIdx.x;
    if (t >= HEADS * SEQ * SEQ) return;
    int h = t / (SEQ * SEQ);
    int r = t - h * (SEQ * SEQ);
    int q = r / SEQ;
    int k = r - q * SEQ;
    int qr = q / GRID_SZ, qc = q - qr * GRID_SZ;
    int kr = k / GRID_SZ, kc = k - kr * GRID_SZ;
    int dr = kr - qr, dc = kc - qc;
    int idx = (dr + GRID_SZ - 1) * MSIZE + (dc + GRID_SZ - 1);
    float v = rel_table[idx * HEADS + h];
    int cheb = max(abs(dr), abs(dc));
    if (cheb > MASK_D) v += -100.0f;
    g_bm[t] = v;
}

// ---------------------------------------------------------------------------
// bf16x3 tensor-core GEMM:
//   C[M,Nt] = (Ah+Al)[M,768] @ (Bh+Bl)[Nt,768]^T + bias  (drop Al*Bl)
// 128x128x32 CTA tile, 8 warps (2m x 4n), warp 64x32, m16n8k16 frags,
// cp.async double-buffered; stride-40 bf16 rows (conflict-free).
// ---------------------------------------------------------------------------
#define KDIM 768
#define GBK  32
#define NST  (KDIM / GBK)            // 24
#define TROW 40                      // bf16 per smem tile row (32 + 8 pad)
#define TILE_BYTES (128 * TROW * 2)  // 10240
#define STAGE_BYTES (4 * TILE_BYTES) // Ah,Al,Bh,Bl = 40960
#define G_SMEM_BYTES (2 * STAGE_BYTES) // 81920

__global__ __launch_bounds__(256, 2)
void gemm_bf16x3(const __nv_bfloat16* __restrict__ Ah,
                 const __nv_bfloat16* __restrict__ Al,
                 const __nv_bfloat16* __restrict__ Bh,
                 const __nv_bfloat16* __restrict__ Bl,
                 const float* __restrict__ bias, float* __restrict__ C, int Nt) {
    extern __shared__ __nv_bfloat16 smb[];
    const uint32_t smem0 = (uint32_t)__cvta_generic_to_shared(smb);

    const int tid = threadIdx.x;
    const int wid = tid >> 5;
    const int lane = tid & 31;
    const int g = lane >> 2;
    const int tig = lane & 3;
    const int wm = wid & 1;
    const int wn = wid >> 1;
    const int tileM = blockIdx.y, tileN = blockIdx.x;

    const __nv_bfloat16* Abh = Ah + (size_t)tileM * 128 * KDIM;
    const __nv_bfloat16* Abl = Al + (size_t)tileM * 128 * KDIM;
    const __nv_bfloat16* Bbh = Bh + (size_t)tileN * 128 * KDIM;
    const __nv_bfloat16* Bbl = Bl + (size_t)tileN * 128 * KDIM;

    float acc[4][4][4];
#pragma unroll
    for (int i = 0; i < 4; i++)
#pragma unroll
        for (int j = 0; j < 4; j++)
#pragma unroll
            for (int r = 0; r < 4; r++) acc[i][j][r] = 0.0f;

    auto issue = [&](int s, int buf) {
        const int k0 = s * GBK;
        const uint32_t base = smem0 + buf * STAGE_BYTES;
#pragma unroll
        for (int rep = 0; rep < 2; rep++) {
            int c = tid + rep * 256;
            int row = c >> 2, ch = c & 3;
            uint32_t soff = (uint32_t)(row * TROW + ch * 8) * 2;
            size_t goff = (size_t)row * KDIM + k0 + ch * 8;
            cp_async16(base + 0 * TILE_BYTES + soff, Abh + goff);
            cp_async16(base + 1 * TILE_BYTES + soff, Abl + goff);
            cp_async16(base + 2 * TILE_BYTES + soff, Bbh + goff);
            cp_async16(base + 3 * TILE_BYTES + soff, Bbl + goff);
        }
        cp_commit();
    };

    issue(0, 0);

    // per-thread fragment element-offset bases (in bf16 elements)
    const int aoff = (wm * 64 + g) * TROW + 2 * tig;
    const int boff = (wn * 32 + g) * TROW + 2 * tig;

    int buf = 0;
    for (int s = 0; s < NST; s++) {
        cp_wait0();
        __syncthreads();
        if (s + 1 < NST) issue(s + 1, buf ^ 1);

        const __nv_bfloat16* Ahs = smb + (size_t)buf * (STAGE_BYTES / 2);
        const __nv_bfloat16* Als = Ahs + TILE_BYTES / 2;
        const __nv_bfloat16* Bhs = Ahs + 2 * (TILE_BYTES / 2);
        const __nv_bfloat16* Bls = Ahs + 3 * (TILE_BYTES / 2);

#pragma unroll
        for (int k16 = 0; k16 < 2; k16++) {
            const int kk = k16 * 16;
            uint32_t ah[4][4], al[4][4];
#pragma unroll
            for (int i = 0; i < 4; i++) {
                const __nv_bfloat16* pah = Ahs + aoff + i * 16 * TROW + kk;
                const __nv_bfloat16* pal = Als + aoff + i * 16 * TROW + kk;
                ah[i][0] = *(const uint32_t*)(pah);
                ah[i][1] = *(const uint32_t*)(pah + 8 * TROW);
                ah[i][2] = *(const uint32_t*)(pah + 8);
                ah[i][3] = *(const uint32_t*)(pah + 8 * TROW + 8);
                al[i][0] = *(const uint32_t*)(pal);
                al[i][1] = *(const uint32_t*)(pal + 8 * TROW);
                al[i][2] = *(const uint32_t*)(pal + 8);
                al[i][3] = *(const uint32_t*)(pal + 8 * TROW + 8);
            }
#pragma unroll
            for (int j = 0; j < 4; j++) {
                const __nv_bfloat16* pbh = Bhs + boff + j * 8 * TROW + kk;
                const __nv_bfloat16* pbl = Bls + boff + j * 8 * TROW + kk;
                uint32_t bh0 = *(const uint32_t*)(pbh);
                uint32_t bh1 = *(const uint32_t*)(pbh + 8);
                uint32_t bl0 = *(const uint32_t*)(pbl);
                uint32_t bl1 = *(const uint32_t*)(pbl + 8);
#pragma unroll
                for (int i = 0; i < 4; i++) {
                    mma_bf16(acc[i][j], al[i][0], al[i][1], al[i][2], al[i][3], bh0, bh1);
                    mma_bf16(acc[i][j], ah[i][0], ah[i][1], ah[i][2], ah[i][3], bl0, bl1);
                    mma_bf16(acc[i][j], ah[i][0], ah[i][1], ah[i][2], ah[i][3], bh0, bh1);
                }
            }
        }
        __syncthreads();
        buf ^= 1;
    }

    // epilogue: c0:(g,2t) c1:(g,2t+1) c2:(g+8,2t) c3:(g+8,2t+1)
#pragma unroll
    for (int i = 0; i < 4; i++) {
        const int row = tileM * 128 + wm * 64 + i * 16 + g;
#pragma unroll
        for (int j = 0; j < 4; j++) {
            const int col = tileN * 128 + wn * 32 + j * 8 + 2 * tig;
            const float b0 = bias[col], b1 = bias[col + 1];
            float2 lo = make_float2(acc[i][j][0] + b0, acc[i][j][1] + b1);
            float2 hi = make_float2(acc[i][j][2] + b0, acc[i][j][3] + b1);
            *(float2*)(C + (size_t)row * Nt + col) = lo;
            *(float2*)(C + (size_t)(row + 8) * Nt + col) = hi;
        }
    }
}

// ---------------------------------------------------------------------------
// Kernel: flash attention (fp32 f32x2) — unchanged (verified at 6e-7 rel err)
// ---------------------------------------------------------------------------
#define AT_SMEM_FLOATS (4096 + 4096 + 64 * 65 + 64 + 64 + 64 + 256)
#define AT_SMEM_BYTES  (AT_SMEM_FLOATS * 4)

__global__ __launch_bounds__(256) void attn_kernel() {
    extern __shared__ float sm[];
    float* sQ  = sm;
    float* sKV = sm + 4096;
    float* sS  = sm + 8192;
    float* m_s = sm + 8192 + 64 * 65;
    float* l_s = m_s + 64;
    float* rsc = l_s + 64;
    float* red = rsc + 64;

    const int tid = threadIdx.x;
    const int tx = tid & 15, ty = tid >> 4;
    const int qt = blockIdx.x, h = blockIdx.y, b = blockIdx.z;
    const int q0 = qt * 64;

    const float* qkvBase = g_qkv + (size_t)b * SEQ * QKV_COLS;
    const int hoff = h * HD;

    {
        const int d0 = tx << 2;
#pragma unroll
        for (int p = 0; p < 4; p++) {
            int n = p * 16 + ty;
            float4 v = *(const float4*)(qkvBase + (size_t)(q0 + n) * QKV_COLS + hoff + d0);
            int gr = (n >> 2) ^ tx;
            int base = gr * 4 + (n & 3);
            sQ[(d0 + 0) * 64 + base] = v.x;
            sQ[(d0 + 1) * 64 + base] = v.y;
            sQ[(d0 + 2) * 64 + base] = v.z;
            sQ[(d0 + 3) * 64 + base] = v.w;
        }
    }
    if (tid < 64) { m_s[tid] = -1e30f; l_s[tid] = 0.0f; }

    unsigned long long accO[4][2];
#pragma unroll
    for (int i = 0; i < 4; i++) { accO[i][0] = 0ull; accO[i][1] = 0ull; }

    for (int kt = 0; kt < SEQ / 64; kt++) {
        const int k0 = kt * 64;
        __syncthreads();

        {
            const int d0 = tx << 2;
#pragma unroll
            for (int p = 0; p < 4; p++) {
                int n = p * 16 + ty;
                float4 v = *(const float4*)(qkvBase + (size_t)(k0 + n) * QKV_COLS + CDIM + hoff + d0);
                int gr = (n >> 2) ^ tx;
                int base = gr * 4 + (n & 3);
                sKV[(d0 + 0) * 64 + base] = v.x;
                sKV[(d0 + 1) * 64 + base] = v.y;
                sKV[(d0 + 2) * 64 + base] = v.z;
                sKV[(d0 + 3) * 64 + base] = v.w;
            }
        }
        __syncthreads();

        unsigned long long accS[4][2];
#pragma unroll
        for (int i = 0; i < 4; i++) { accS[i][0] = 0ull; accS[i][1] = 0ull; }
#pragma unroll 8
        for (int d = 0; d < 64; d++) {
            int sw = (d >> 2) & 15;
            float4 a = *(const float4*)&sQ[d * 64 + ((ty ^ sw) << 2)];
            ulonglong2 bv = *(const ulonglong2*)&sKV[d * 64 + ((tx ^ sw) << 2)];
            unsigned long long a0 = splat2(a.x), a1 = splat2(a.y),
                               a2 = splat2(a.z), a3 = splat2(a.w);
            ffma2(accS[0][0], a0, bv.x); ffma2(accS[0][1], a0, bv.y);
            ffma2(accS[1][0], a1, bv.x); ffma2(accS[1][1], a1, bv.y);
            ffma2(accS[2][0], a2, bv.x); ffma2(accS[2][1], a2, bv.y);
            ffma2(accS[3][0], a3, bv.x); ffma2(accS[3][1], a3, bv.y);
        }

        {
            const float* bmrow = g_bm + ((size_t)h * SEQ + (q0 + ty * 4)) * SEQ + k0 + tx * 4;
#pragma unroll
            for (int i = 0; i < 4; i++) {
                float2 s0 = unpk(accS[i][0]);
                float2 s1 = unpk(accS[i][1]);
                const float* bmp = bmrow + (size_t)i * SEQ;
                float* srow = &sS[(ty * 4 + i) * 65 + tx * 4];
                srow[0] = fmaf(s0.x, SOFT_SCALE, bmp[0]);
                srow[1] = fmaf(s0.y, SOFT_SCALE, bmp[1]);
                srow[2] = fmaf(s1.x, SOFT_SCALE, bmp[2]);
                srow[3] = fmaf(s1.y, SOFT_SCALE, bmp[3]);
            }
        }
        __syncthreads();

        {
            const int d0 = tx << 2;
#pragma unroll
            for (int p = 0; p < 4; p++) {
                int n = p * 16 + ty;
                float4 v = *(const float4*)(qkvBase + (size_t)(k0 + n) * QKV_COLS + 2 * CDIM + hoff + d0);
                *(float4*)&sKV[n * 64 + d0] = v;
            }
        }
        {
            int r = tid & 63, seg = tid >> 6;
            const float* srow = &sS[r * 65 + seg * 16];
            float pm = srow[0];
#pragma unroll
            for (int j = 1; j < 16; j++) pm = fmaxf(pm, srow[j]);
            red[seg * 64 + r] = pm;
        }
        __syncthreads();
        if (tid < 64) {
            int r = tid;
            float mn = fmaxf(fmaxf(red[r], red[64 + r]), fmaxf(red[128 + r], red[192 + r]));
            float mo = m_s[r];
            mn = fmaxf(mo, mn);
            m_s[r] = mn;
            rsc[r] = __expf(mo - mn);
        }
        __syncthreads();
        {
            int r = tid & 63, seg = tid >> 6;
            float mr = m_s[r];
            float* srow = &sS[r * 65 + seg * 16];
            float ps = 0.0f;
#pragma unroll
            for (int j = 0; j < 16; j++) {
                float e = __expf(srow[j] - mr);
                srow[j] = e;
                ps += e;
            }
            red[seg * 64 + r] = ps;
        }
        __syncthreads();
        if (tid < 64) {
            int r = tid;
            l_s[r] = l_s[r] * rsc[r] + (red[r] + red[64 + r]) + (red[128 + r] + red[192 + r]);
        }

#pragma unroll
        for (int i = 0; i < 4; i++) {
            unsigned long long sc2 = splat2(rsc[ty * 4 + i]);
            fmul2(accO[i][0], sc2);
            fmul2(accO[i][1], sc2);
        }
#pragma unroll 8
        for (int k = 0; k < 64; k++) {
            ulonglong2 vv = *(const ulonglong2*)&sKV[k * 64 + tx * 4];
            unsigned long long p0 = splat2(sS[(ty * 4 + 0) * 65 + k]);
            unsigned long long p1 = splat2(sS[(ty * 4 + 1) * 65 + k]);
            unsigned long long p2 = splat2(sS[(ty * 4 + 2) * 65 + k]);
            unsigned long long p3 = splat2(sS[(ty * 4 + 3) * 65 + k]);
            ffma2(accO[0][0], p0, vv.x); ffma2(accO[0][1], p0, vv.y);
            ffma2(accO[1][0], p1, vv.x); ffma2(accO[1][1], p1, vv.y);
            ffma2(accO[2][0], p2, vv.x); ffma2(accO[2][1], p2, vv.y);
            ffma2(accO[3][0], p3, vv.x); ffma2(accO[3][1], p3, vv.y);
        }
    }
    __syncthreads();

#pragma unroll
    for (int i = 0; i < 4; i++) {
        float inv = 1.0f / l_s[ty * 4 + i];
        float2 o0 = unpk(accO[i][0]);
        float2 o1 = unpk(accO[i][1]);
        float4 out = make_float4(o0.x * inv, o0.y * inv, o1.x * inv, o1.y * inv);
        *(float4*)(g_x2 + (size_t)(b * SEQ + q0 + ty * 4 + i) * CDIM + hoff + tx * 4) = out;
    }
}

// ---------------------------------------------------------------------------
// Launch
// ---------------------------------------------------------------------------
extern "C" void kernel_launch(void* const* d_in, const int* in_sizes, int n_in,
                              void* d_out, int out_size) {
    const float* x         = (const float*)d_in[0];
    const float* w_qkv     = (const float*)d_in[1];
    const float* b_qkv     = (const float*)d_in[2];
    const float* rel_table = (const float*)d_in[3];
    const float* w_proj    = (const float*)d_in[4];
    const float* b_proj    = (const float*)d_in[5];
    float* out = (float*)d_out;

    float *pqkv, *px2;
    __nv_bfloat16 *pxh, *pxl, *px2h, *px2l, *pwqh, *pwql, *pwph, *pwpl;
    cudaGetSymbolAddress((void**)&pqkv, g_qkv);
    cudaGetSymbolAddress((void**)&px2, g_x2);
    cudaGetSymbolAddress((void**)&pxh, g_xh);
    cudaGetSymbolAddress((void**)&pxl, g_xl);
    cudaGetSymbolAddress((void**)&px2h, g_x2h);
    cudaGetSymbolAddress((void**)&px2l, g_x2l);
    cudaGetSymbolAddress((void**)&pwqh, g_wqkvTh);
    cudaGetSymbolAddress((void**)&pwql, g_wqkvTl);
    cudaGetSymbolAddress((void**)&pwph, g_wprojTh);
    cudaGetSymbolAddress((void**)&pwpl, g_wprojTl);

    cudaFuncSetAttribute(attn_kernel, cudaFuncAttributeMaxDynamicSharedMemorySize,
                         AT_SMEM_BYTES);
    cudaFuncSetAttribute(gemm_bf16x3, cudaFuncAttributeMaxDynamicSharedMemorySize,
                         G_SMEM_BYTES);

    const int N4 = MROWS * CDIM / 4;

    // 0) split x; transpose+split weights; bias/mask precompute
    split_kernel<<<(N4 + 255) / 256, 256>>>(x, pxh, pxl, N4);
    transpose_split_kernel<<<dim3(QKV_COLS / 32, CDIM / 32), dim3(32, 8)>>>(
        w_qkv, pwqh, pwql, CDIM, QKV_COLS);
    transpose_split_kernel<<<dim3(CDIM / 32, CDIM / 32), dim3(32, 8)>>>(
        w_proj, pwph, pwpl, CDIM, CDIM);
    biasmask_kernel<<<(HEADS * SEQ * SEQ + 255) / 256, 256>>>(rel_table);

    // 1) QKV projection: [18432,768] @ [768,2304]  (bf16x3 mma.sync)
    gemm_bf16x3<<<dim3(QKV_COLS / 128, MROWS / 128), 256, G_SMEM_BYTES>>>(
        pxh, pxl, pwqh, pwql, b_qkv, pqkv, QKV_COLS);

    // 2) attention (fp32)
    attn_kernel<<<dim3(SEQ / 64, HEADS, BATCH), 256, AT_SMEM_BYTES>>>();

    // 3) split attention output, then output projection (bf16x3 mma.sync)
    split_kernel<<<(N4 + 255) / 256, 256>>>(px2, px2h, px2l, N4);
    gemm_bf16x3<<<dim3(CDIM / 128, MROWS / 128), 256, G_SMEM_BYTES>>>(
        px2h, px2l, pwph, pwpl, b_proj, out, CDIM);
}

// round 6
// speedup vs baseline: 2.1687x; 1.1866x over previous
#include <cuda_runtime.h>
#include <cuda_bf16.h>
#include <cstdint>

// ---------------------------------------------------------------------------
// Problem dimensions (fixed by the reference)
// ---------------------------------------------------------------------------
#define BATCH     32
#define HEADS     12
#define SEQ       576
#define HD        64
#define CDIM      768
#define MROWS     (BATCH * SEQ)      // 18432
#define QKV_COLS  (3 * CDIM)         // 2304
#define GRID_SZ   24
#define MSIZE     47
#define MASK_D    12
#define SOFT_SCALE 0.125f

// ---------------------------------------------------------------------------
// Scratch (device globals)
// ---------------------------------------------------------------------------
__device__ float g_bm[(size_t)HEADS * SEQ * SEQ];                 // 16 MB
__device__ __nv_bfloat16 g_qkvh[(size_t)MROWS * QKV_COLS];        // 85 MB
__device__ __nv_bfloat16 g_qkvl[(size_t)MROWS * QKV_COLS];        // 85 MB
__device__ __nv_bfloat16 g_xh[(size_t)MROWS * CDIM];
__device__ __nv_bfloat16 g_xl[(size_t)MROWS * CDIM];
__device__ __nv_bfloat16 g_x2h[(size_t)MROWS * CDIM];
__device__ __nv_bfloat16 g_x2l[(size_t)MROWS * CDIM];
__device__ __nv_bfloat16 g_wqkvTh[(size_t)QKV_COLS * CDIM];
__device__ __nv_bfloat16 g_wqkvTl[(size_t)QKV_COLS * CDIM];
__device__ __nv_bfloat16 g_wprojTh[(size_t)CDIM * CDIM];
__device__ __nv_bfloat16 g_wprojTl[(size_t)CDIM * CDIM];

// ---------------------------------------------------------------------------
// Helpers
// ---------------------------------------------------------------------------
__device__ __forceinline__ void cp_async16(uint32_t smem_dst, const void* gptr) {
    asm volatile("cp.async.cg.shared.global [%0], [%1], 16;"
                 :: "r"(smem_dst), "l"(gptr));
}
__device__ __forceinline__ void cp_commit() { asm volatile("cp.async.commit_group;"); }
__device__ __forceinline__ void cp_wait0()  { asm volatile("cp.async.wait_group 0;"); }
__device__ __forceinline__ void cp_wait1()  { asm volatile("cp.async.wait_group 1;"); }

__device__ __forceinline__ void mma_bf16(
    float* c, uint32_t a0, uint32_t a1, uint32_t a2, uint32_t a3,
    uint32_t b0, uint32_t b1)
{
    asm volatile(
        "mma.sync.aligned.m16n8k16.row.col.f32.bf16.bf16.f32 "
        "{%0,%1,%2,%3}, {%4,%5,%6,%7}, {%8,%9}, {%0,%1,%2,%3};"
        : "+f"(c[0]), "+f"(c[1]), "+f"(c[2]), "+f"(c[3])
        : "r"(a0), "r"(a1), "r"(a2), "r"(a3), "r"(b0), "r"(b1));
}

__device__ __forceinline__ void ldsm_x4_t(uint32_t& r0, uint32_t& r1,
                                          uint32_t& r2, uint32_t& r3,
                                          uint32_t addr) {
    asm volatile("ldmatrix.sync.aligned.m8n8.x4.trans.shared.b16 {%0,%1,%2,%3}, [%4];"
                 : "=r"(r0), "=r"(r1), "=r"(r2), "=r"(r3) : "r"(addr));
}

__device__ __forceinline__ void split_bf16(float v, __nv_bfloat16& h, __nv_bfloat16& l) {
    h = __float2bfloat16(v);
    l = __float2bfloat16(v - __bfloat162float(h));
}

// ---------------------------------------------------------------------------
// Kernel: elementwise split fp32 -> bf16 hi/lo (x input)
// ---------------------------------------------------------------------------
__global__ void split_kernel(const float* __restrict__ in,
                             __nv_bfloat16* __restrict__ hi,
                             __nv_bfloat16* __restrict__ lo, int n4) {
    int t = blockIdx.x * 256 + threadIdx.x;
    if (t >= n4) return;
    float4 v = *(const float4*)(in + (size_t)t * 4);
    __nv_bfloat16 h[4], l[4];
    split_bf16(v.x, h[0], l[0]);
    split_bf16(v.y, h[1], l[1]);
    split_bf16(v.z, h[2], l[2]);
    split_bf16(v.w, h[3], l[3]);
    *(ushort4*)(hi + (size_t)t * 4) = *(ushort4*)h;
    *(ushort4*)(lo + (size_t)t * 4) = *(ushort4*)l;
}

// ---------------------------------------------------------------------------
// Kernel: weight transpose src[R][C] -> dstH/dstL[C][R] (bf16 hi/lo)
// ---------------------------------------------------------------------------
__global__ void transpose_split_kernel(const float* __restrict__ src,
                                       __nv_bfloat16* __restrict__ dstH,
                                       __nv_bfloat16* __restrict__ dstL,
                                       int R, int C) {
    __shared__ float t[32][33];
    int bx = blockIdx.x * 32, by = blockIdx.y * 32;
#pragma unroll
    for (int i = 0; i < 32; i += 8)
        t[threadIdx.y + i][threadIdx.x] =
            src[(size_t)(by + threadIdx.y + i) * C + bx + threadIdx.x];
    __syncthreads();
#pragma unroll
    for (int i = 0; i < 32; i += 8) {
        float v = t[threadIdx.x][threadIdx.y + i];
        __nv_bfloat16 h, l;
        split_bf16(v, h, l);
        size_t o = (size_t)(bx + threadIdx.y + i) * R + by + threadIdx.x;
        dstH[o] = h;
        dstL[o] = l;
    }
}

// ---------------------------------------------------------------------------
// Kernel: precompute bias + mask  ->  g_bm[h][q][k]
// ---------------------------------------------------------------------------
__global__ void biasmask_kernel(const float* __restrict__ rel_table) {
    int t = blockIdx.x * 256 + threadIdx.x;
    if (t >= HEADS * SEQ * SEQ) return;
    int h = t / (SEQ * SEQ);
    int r = t - h * (SEQ * SEQ);
    int q = r / SEQ;
    int k = r - q * SEQ;
    int qr = q / GRID_SZ, qc = q - qr * GRID_SZ;
    int kr = k / GRID_SZ, kc = k - kr * GRID_SZ;
    int dr = kr - qr, dc = kc - qc;
    int idx = (dr + GRID_SZ - 1) * MSIZE + (dc + GRID_SZ - 1);
    float v = rel_table[idx * HEADS + h];
    int cheb = max(abs(dr), abs(dc));
    if (cheb > MASK_D) v += -100.0f;
    g_bm[t] = v;
}

// ---------------------------------------------------------------------------
// bf16x3 tensor-core GEMM: C = (Ah+Al)[M,768] @ (Bh+Bl)[Nt,768]^T + bias
// Output either fp32 (Cf) or hi/lo bf16 split (Ch/Cl).
// ---------------------------------------------------------------------------
#define KDIM 768
#define GBK  32
#define NST  (KDIM / GBK)
#define TROW 40
#define TILE_BYTES (128 * TROW * 2)
#define STAGE_BYTES (4 * TILE_BYTES)
#define G_SMEM_BYTES (2 * STAGE_BYTES)

__global__ __launch_bounds__(256, 2)
void gemm_bf16x3(const __nv_bfloat16* __restrict__ Ah,
                 const __nv_bfloat16* __restrict__ Al,
                 const __nv_bfloat16* __restrict__ Bh,
                 const __nv_bfloat16* __restrict__ Bl,
                 const float* __restrict__ bias,
                 float* __restrict__ Cf,
                 __nv_bfloat16* __restrict__ Ch,
                 __nv_bfloat16* __restrict__ Cl, int Nt) {
    extern __shared__ __nv_bfloat16 smb[];
    const uint32_t smem0 = (uint32_t)__cvta_generic_to_shared(smb);

    const int tid = threadIdx.x;
    const int wid = tid >> 5;
    const int lane = tid & 31;
    const int g = lane >> 2;
    const int tig = lane & 3;
    const int wm = wid & 1;
    const int wn = wid >> 1;
    const int tileM = blockIdx.y, tileN = blockIdx.x;

    const __nv_bfloat16* Abh = Ah + (size_t)tileM * 128 * KDIM;
    const __nv_bfloat16* Abl = Al + (size_t)tileM * 128 * KDIM;
    const __nv_bfloat16* Bbh = Bh + (size_t)tileN * 128 * KDIM;
    const __nv_bfloat16* Bbl = Bl + (size_t)tileN * 128 * KDIM;

    float acc[4][4][4];
#pragma unroll
    for (int i = 0; i < 4; i++)
#pragma unroll
        for (int j = 0; j < 4; j++)
#pragma unroll
            for (int r = 0; r < 4; r++) acc[i][j][r] = 0.0f;

    auto issue = [&](int s, int buf) {
        const int k0 = s * GBK;
        const uint32_t base = smem0 + buf * STAGE_BYTES;
#pragma unroll
        for (int rep = 0; rep < 2; rep++) {
            int c = tid + rep * 256;
            int row = c >> 2, ch = c & 3;
            uint32_t soff = (uint32_t)(row * TROW + ch * 8) * 2;
            size_t goff = (size_t)row * KDIM + k0 + ch * 8;
            cp_async16(base + 0 * TILE_BYTES + soff, Abh + goff);
            cp_async16(base + 1 * TILE_BYTES + soff, Abl + goff);
            cp_async16(base + 2 * TILE_BYTES + soff, Bbh + goff);
            cp_async16(base + 3 * TILE_BYTES + soff, Bbl + goff);
        }
        cp_commit();
    };

    issue(0, 0);

    const int aoff = (wm * 64 + g) * TROW + 2 * tig;
    const int boff = (wn * 32 + g) * TROW + 2 * tig;

    int buf = 0;
    for (int s = 0; s < NST; s++) {
        cp_wait0();
        __syncthreads();
        if (s + 1 < NST) issue(s + 1, buf ^ 1);

        const __nv_bfloat16* Ahs = smb + (size_t)buf * (STAGE_BYTES / 2);
        const __nv_bfloat16* Als = Ahs + TILE_BYTES / 2;
        const __nv_bfloat16* Bhs = Ahs + 2 * (TILE_BYTES / 2);
        const __nv_bfloat16* Bls = Ahs + 3 * (TILE_BYTES / 2);

#pragma unroll
        for (int k16 = 0; k16 < 2; k16++) {
            const int kk = k16 * 16;
            uint32_t ah[4][4], al[4][4];
#pragma unroll
            for (int i = 0; i < 4; i++) {
                const __nv_bfloat16* pah = Ahs + aoff + i * 16 * TROW + kk;
                const __nv_bfloat16* pal = Als + aoff + i * 16 * TROW + kk;
                ah[i][0] = *(const uint32_t*)(pah);
                ah[i][1] = *(const uint32_t*)(pah + 8 * TROW);
                ah[i][2] = *(const uint32_t*)(pah + 8);
                ah[i][3] = *(const uint32_t*)(pah + 8 * TROW + 8);
                al[i][0] = *(const uint32_t*)(pal);
                al[i][1] = *(const uint32_t*)(pal + 8 * TROW);
                al[i][2] = *(const uint32_t*)(pal + 8);
                al[i][3] = *(const uint32_t*)(pal + 8 * TROW + 8);
            }
#pragma unroll
            for (int j = 0; j < 4; j++) {
                const __nv_bfloat16* pbh = Bhs + boff + j * 8 * TROW + kk;
                const __nv_bfloat16* pbl = Bls + boff + j * 8 * TROW + kk;
                uint32_t bh0 = *(const uint32_t*)(pbh);
                uint32_t bh1 = *(const uint32_t*)(pbh + 8);
                uint32_t bl0 = *(const uint32_t*)(pbl);
                uint32_t bl1 = *(const uint32_t*)(pbl + 8);
#pragma unroll
                for (int i = 0; i < 4; i++) {
                    mma_bf16(acc[i][j], al[i][0], al[i][1], al[i][2], al[i][3], bh0, bh1);
                    mma_bf16(acc[i][j], ah[i][0], ah[i][1], ah[i][2], ah[i][3], bl0, bl1);
                    mma_bf16(acc[i][j], ah[i][0], ah[i][1], ah[i][2], ah[i][3], bh0, bh1);
                }
            }
        }
        __syncthreads();
        buf ^= 1;
    }

#pragma unroll
    for (int i = 0; i < 4; i++) {
        const int row = tileM * 128 + wm * 64 + i * 16 + g;
#pragma unroll
        for (int j = 0; j < 4; j++) {
            const int col = tileN * 128 + wn * 32 + j * 8 + 2 * tig;
            const float b0 = bias[col], b1 = bias[col + 1];
            float v0 = acc[i][j][0] + b0, v1 = acc[i][j][1] + b1;
            float v2 = acc[i][j][2] + b0, v3 = acc[i][j][3] + b1;
            if (Cf) {
                *(float2*)(Cf + (size_t)row * Nt + col) = make_float2(v0, v1);
                *(float2*)(Cf + (size_t)(row + 8) * Nt + col) = make_float2(v2, v3);
            } else {
                __nv_bfloat16 h[2], l[2];
                split_bf16(v0, h[0], l[0]); split_bf16(v1, h[1], l[1]);
                *(ushort2*)(Ch + (size_t)row * Nt + col) = *(ushort2*)h;
                *(ushort2*)(Cl + (size_t)row * Nt + col) = *(ushort2*)l;
                split_bf16(v2, h[0], l[0]); split_bf16(v3, h[1], l[1]);
                *(ushort2*)(Ch + (size_t)(row + 8) * Nt + col) = *(ushort2*)h;
                *(ushort2*)(Cl + (size_t)(row + 8) * Nt + col) = *(ushort2*)l;
            }
        }
    }
}

// ---------------------------------------------------------------------------
// Flash attention, bf16x3 tensor cores.
// Block = (b, h, 64-q-tile), 256 threads, 8 warps (4m x 2n).
// ---------------------------------------------------------------------------
#define QK_STR 72          // bf16 stride for Q/K/V tiles
#define P_STR  66          // bf16 stride for P tiles
#define SS_STR 65          // fp32 stride for scores
#define NKT    (SEQ / 64)  // 9

// smem layout (bf16 elems unless noted)
#define OFF_QH  0
#define OFF_QL  (OFF_QH + 64 * QK_STR)
#define OFF_KH  (OFF_QL + 64 * QK_STR)
#define OFF_KL  (OFF_KH + 64 * QK_STR)
#define OFF_VH  (OFF_KL + 64 * QK_STR)
#define OFF_VL  (OFF_VH + 64 * QK_STR)
#define OFF_PH  (OFF_VL + 64 * QK_STR)
#define OFF_PL  (OFF_PH + 64 * P_STR)
#define OFF_F32 (OFF_PL + 64 * P_STR)   // fp32 region starts (bf16 idx, even)
#define SS_F    0
#define MS_F    (SS_F + 64 * SS_STR)
#define LS_F    (MS_F + 64)
#define RS_F    (LS_F + 64)
#define RED_F   (RS_F + 64)
#define AT_SMEM_BYTES (OFF_F32 * 2 + (RED_F + 256) * 4)

__global__ __launch_bounds__(256, 2) void attn_kernel() {
    extern __shared__ __nv_bfloat16 smraw[];
    __nv_bfloat16* sQh = smraw + OFF_QH;
    __nv_bfloat16* sQl = smraw + OFF_QL;
    __nv_bfloat16* sKh = smraw + OFF_KH;
    __nv_bfloat16* sKl = smraw + OFF_KL;
    __nv_bfloat16* sVh = smraw + OFF_VH;
    __nv_bfloat16* sVl = smraw + OFF_VL;
    __nv_bfloat16* sPh = smraw + OFF_PH;
    __nv_bfloat16* sPl = smraw + OFF_PL;
    float* sS  = (float*)(smraw + OFF_F32) + SS_F;
    float* m_s = (float*)(smraw + OFF_F32) + MS_F;
    float* l_s = (float*)(smraw + OFF_F32) + LS_F;
    float* rsc = (float*)(smraw + OFF_F32) + RS_F;
    float* red = (float*)(smraw + OFF_F32) + RED_F;

    const uint32_t smemU = (uint32_t)__cvta_generic_to_shared(smraw);

    const int tid = threadIdx.x;
    const int wid = tid >> 5;
    const int lane = tid & 31;
    const int g = lane >> 2;
    const int tig = lane & 3;
    const int wm = wid & 3;          // 0..3
    const int wn = wid >> 2;         // 0..1
    const int m0 = wm * 16;
    const int n0 = wn * 32;

    const int qt = blockIdx.x, h = blockIdx.y, b = blockIdx.z;
    const int q0 = qt * 64;
    const int hoff = h * HD;
    const size_t rowBase = (size_t)b * SEQ;

    // ---- prologue: load Q (hi/lo) and K tile 0 via cp.async
    {
#pragma unroll
        for (int rep = 0; rep < 2; rep++) {
            int c = tid + rep * 256;
            int row = c >> 3, ch = c & 7;
            uint32_t soff = (uint32_t)(row * QK_STR + ch * 8) * 2;
            size_t gq = (rowBase + q0 + row) * QKV_COLS + hoff + ch * 8;
            size_t gk = (rowBase + 0 + row) * QKV_COLS + CDIM + hoff + ch * 8;
            cp_async16(smemU + OFF_QH * 2 + soff, g_qkvh + gq);
            cp_async16(smemU + OFF_QL * 2 + soff, g_qkvl + gq);
            cp_async16(smemU + OFF_KH * 2 + soff, g_qkvh + gk);
            cp_async16(smemU + OFF_KL * 2 + soff, g_qkvl + gk);
        }
        cp_commit();
    }
    if (tid < 64) { m_s[tid] = -1e30f; l_s[tid] = 0.0f; }

    float accO[4][4];
#pragma unroll
    for (int j = 0; j < 4; j++)
#pragma unroll
        for (int r = 0; r < 4; r++) accO[j][r] = 0.0f;

    for (int kt = 0; kt < NKT; kt++) {
        const int k0 = kt * 64;
        cp_wait0();
        __syncthreads();

        // ---- S = Q @ K^T (bf16x3)
        float sacc[4][4];
#pragma unroll
        for (int j = 0; j < 4; j++)
#pragma unroll
            for (int r = 0; r < 4; r++) sacc[j][r] = 0.0f;

#pragma unroll
        for (int kk4 = 0; kk4 < 4; kk4++) {
            const int kk = kk4 * 16;
            const int abase = (m0 + g) * QK_STR + kk + 2 * tig;
            uint32_t qh[4], ql[4];
            qh[0] = *(const uint32_t*)(sQh + abase);
            qh[1] = *(const uint32_t*)(sQh + abase + 8 * QK_STR);
            qh[2] = *(const uint32_t*)(sQh + abase + 8);
            qh[3] = *(const uint32_t*)(sQh + abase + 8 * QK_STR + 8);
            ql[0] = *(const uint32_t*)(sQl + abase);
            ql[1] = *(const uint32_t*)(sQl + abase + 8 * QK_STR);
            ql[2] = *(const uint32_t*)(sQl + abase + 8);
            ql[3] = *(const uint32_t*)(sQl + abase + 8 * QK_STR + 8);
#pragma unroll
            for (int j = 0; j < 4; j++) {
                const int bbase = (n0 + j * 8 + g) * QK_STR + kk + 2 * tig;
                uint32_t kh0 = *(const uint32_t*)(sKh + bbase);
                uint32_t kh1 = *(const uint32_t*)(sKh + bbase + 8);
                uint32_t kl0 = *(const uint32_t*)(sKl + bbase);
                uint32_t kl1 = *(const uint32_t*)(sKl + bbase + 8);
                mma_bf16(sacc[j], ql[0], ql[1], ql[2], ql[3], kh0, kh1);
                mma_bf16(sacc[j], qh[0], qh[1], qh[2], qh[3], kl0, kl1);
                mma_bf16(sacc[j], qh[0], qh[1], qh[2], qh[3], kh0, kh1);
            }
        }

        // ---- scores + bias/mask -> sS (fp32, stride 65)
        {
            const float* bmA = g_bm + ((size_t)h * SEQ + (q0 + m0 + g)) * SEQ + k0 + n0 + 2 * tig;
            const float* bmB = bmA + 8 * SEQ;
#pragma unroll
            for (int j = 0; j < 4; j++) {
                float2 ba = *(const float2*)(bmA + j * 8);
                float2 bb = *(const float2*)(bmB + j * 8);
                int c0 = n0 + j * 8 + 2 * tig;
                sS[(m0 + g) * SS_STR + c0]     = fmaf(sacc[j][0], SOFT_SCALE, ba.x);
                sS[(m0 + g) * SS_STR + c0 + 1] = fmaf(sacc[j][1], SOFT_SCALE, ba.y);
                sS[(m0 + 8 + g) * SS_STR + c0]     = fmaf(sacc[j][2], SOFT_SCALE, bb.x);
                sS[(m0 + 8 + g) * SS_STR + c0 + 1] = fmaf(sacc[j][3], SOFT_SCALE, bb.y);
            }
        }
        __syncthreads();   // S done; all warps done reading K/V buffers

        // ---- prefetch V(kt) then K(kt+1)
        {
#pragma unroll
            for (int rep = 0; rep < 2; rep++) {
                int c = tid + rep * 256;
                int row = c >> 3, ch = c & 7;
                uint32_t soff = (uint32_t)(row * QK_STR + ch * 8) * 2;
                size_t gv = (rowBase + k0 + row) * QKV_COLS + 2 * CDIM + hoff + ch * 8;
                cp_async16(smemU + OFF_VH * 2 + soff, g_qkvh + gv);
                cp_async16(smemU + OFF_VL * 2 + soff, g_qkvl + gv);
            }
            cp_commit();   // group: V
            if (kt + 1 < NKT) {
#pragma unroll
                for (int rep = 0; rep < 2; rep++) {
                    int c = tid + rep * 256;
                    int row = c >> 3, ch = c & 7;
                    uint32_t soff = (uint32_t)(row * QK_STR + ch * 8) * 2;
                    size_t gk = (rowBase + k0 + 64 + row) * QKV_COLS + CDIM + hoff + ch * 8;
                    cp_async16(smemU + OFF_KH * 2 + soff, g_qkvh + gk);
                    cp_async16(smemU + OFF_KL * 2 + soff, g_qkvl + gk);
                }
            }
            cp_commit();   // group: K (possibly empty)
        }

        // ---- softmax: row max
        {
            int r = tid & 63, seg = tid >> 6;
            const float* srow = sS + r * SS_STR + seg * 16;
            float pm = srow[0];
#pragma unroll
            for (int j = 1; j < 16; j++) pm = fmaxf(pm, srow[j]);
            red[seg * 64 + r] = pm;
        }
        __syncthreads();
        if (tid < 64) {
            int r = tid;
            float mn = fmaxf(fmaxf(red[r], red[64 + r]), fmaxf(red[128 + r], red[192 + r]));
            float mo = m_s[r];
            mn = fmaxf(mo, mn);
            m_s[r] = mn;
            rsc[r] = __expf(mo - mn);
        }
        __syncthreads();
        // ---- exp pass -> Ph/Pl (bf16 split), partial sums
        {
            int r = tid & 63, seg = tid >> 6;
            float mr = m_s[r];
            const float* srow = sS + r * SS_STR + seg * 16;
            __nv_bfloat16* ph = sPh + r * P_STR + seg * 16;
            __nv_bfloat16* pl = sPl + r * P_STR + seg * 16;
            float ps = 0.0f;
#pragma unroll
            for (int j = 0; j < 16; j++) {
                float e = __expf(srow[j] - mr);
                __nv_bfloat16 eh, el;
                split_bf16(e, eh, el);
                ph[j] = eh;
                pl[j] = el;
                ps += e;
            }
            red[seg * 64 + r] = ps;
        }
        __syncthreads();
        if (tid < 64) {
            int r = tid;
            l_s[r] = l_s[r] * rsc[r] + (red[r] + red[64 + r]) + (red[128 + r] + red[192 + r]);
        }

        cp_wait1();        // V ready (K group may still be in flight)
        __syncthreads();   // V visible to all; l_s/rsc visible

        // ---- rescale O, then O += P @ V (bf16x3, V via ldmatrix.trans)
        {
            float r0 = rsc[m0 + g], r1 = rsc[m0 + 8 + g];
#pragma unroll
            for (int j = 0; j < 4; j++) {
                accO[j][0] *= r0; accO[j][1] *= r0;
                accO[j][2] *= r1; accO[j][3] *= r1;
            }
        }
        {
            const int quad = lane >> 3, lrow = lane & 7;
            const int ksub = (quad & 1) * 8;
#pragma unroll
            for (int kk4 = 0; kk4 < 4; kk4++) {
                const int kk = kk4 * 16;
                const int pbase = (m0 + g) * P_STR + kk + 2 * tig;
                uint32_t ph[4], pl[4];
                ph[0] = *(const uint32_t*)(sPh + pbase);
                ph[1] = *(const uint32_t*)(sPh + pbase + 8 * P_STR);
                ph[2] = *(const uint32_t*)(sPh + pbase + 8);
                ph[3] = *(const uint32_t*)(sPh + pbase + 8 * P_STR + 8);
                pl[0] = *(const uint32_t*)(sPl + pbase);
                pl[1] = *(const uint32_t*)(sPl + pbase + 8 * P_STR);
                pl[2] = *(const uint32_t*)(sPl + pbase + 8);
                pl[3] = *(const uint32_t*)(sPl + pbase + 8 * P_STR + 8);
#pragma unroll
                for (int jp = 0; jp < 2; jp++) {
                    const int jj = jp * 2 + (quad >> 1);
                    uint32_t vrow = (uint32_t)((kk + ksub + lrow) * QK_STR + n0 + jj * 8) * 2;
                    uint32_t vh0, vh1, vh2, vh3, vl0, vl1, vl2, vl3;
                    ldsm_x4_t(vh0, vh1, vh2, vh3, smemU + OFF_VH * 2 + vrow);
                    ldsm_x4_t(vl0, vl1, vl2, vl3, smemU + OFF_VL * 2 + vrow);
                    float* c0 = accO[jp * 2];
                    float* c1 = accO[jp * 2 + 1];
                    mma_bf16(c0, pl[0], pl[1], pl[2], pl[3], vh0, vh1);
                    mma_bf16(c0, ph[0], ph[1], ph[2], ph[3], vl0, vl1);
                    mma_bf16(c0, ph[0], ph[1], ph[2], ph[3], vh0, vh1);
                    mma_bf16(c1, pl[0], pl[1], pl[2], pl[3], vh2, vh3);
                    mma_bf16(c1, ph[0], ph[1], ph[2], ph[3], vl2, vl3);
                    mma_bf16(c1, ph[0], ph[1], ph[2], ph[3], vh2, vh3);
                }
            }
        }
    }

    // ---- normalize + hi/lo split store to g_x2h/g_x2l
    {
        float inv0 = 1.0f / l_s[m0 + g];
        float inv1 = 1.0f / l_s[m0 + 8 + g];
#pragma unroll
        for (int j = 0; j < 4; j++) {
            int col = hoff + n0 + j * 8 + 2 * tig;
            size_t o0 = (rowBase + q0 + m0 + g) * CDIM + col;
            size_t o1 = (rowBase + q0 + m0 + 8 + g) * CDIM + col;
            __nv_bfloat16 hh[2], ll[2];
            split_bf16(accO[j][0] * inv0, hh[0], ll[0]);
            split_bf16(accO[j][1] * inv0, hh[1], ll[1]);
            *(ushort2*)(g_x2h + o0) = *(ushort2*)hh;
            *(ushort2*)(g_x2l + o0) = *(ushort2*)ll;
            split_bf16(accO[j][2] * inv1, hh[0], ll[0]);
            split_bf16(accO[j][3] * inv1, hh[1], ll[1]);
            *(ushort2*)(g_x2h + o1) = *(ushort2*)hh;
            *(ushort2*)(g_x2l + o1) = *(ushort2*)ll;
        }
    }
}

// ---------------------------------------------------------------------------
// Launch
// ---------------------------------------------------------------------------
extern "C" void kernel_launch(void* const* d_in, const int* in_sizes, int n_in,
                              void* d_out, int out_size) {
    const float* x         = (const float*)d_in[0];
    const float* w_qkv     = (const float*)d_in[1];
    const float* b_qkv     = (const float*)d_in[2];
    const float* rel_table = (const float*)d_in[3];
    const float* w_proj    = (const float*)d_in[4];
    const float* b_proj    = (const float*)d_in[5];
    float* out = (float*)d_out;

    __nv_bfloat16 *pqh, *pql, *pxh, *pxl, *px2h, *px2l, *pwqh, *pwql, *pwph, *pwpl;
    cudaGetSymbolAddress((void**)&pqh, g_qkvh);
    cudaGetSymbolAddress((void**)&pql, g_qkvl);
    cudaGetSymbolAddress((void**)&pxh, g_xh);
    cudaGetSymbolAddress((void**)&pxl, g_xl);
    cudaGetSymbolAddress((void**)&px2h, g_x2h);
    cudaGetSymbolAddress((void**)&px2l, g_x2l);
    cudaGetSymbolAddress((void**)&pwqh, g_wqkvTh);
    cudaGetSymbolAddress((void**)&pwql, g_wqkvTl);
    cudaGetSymbolAddress((void**)&pwph, g_wprojTh);
    cudaGetSymbolAddress((void**)&pwpl, g_wprojTl);

    cudaFuncSetAttribute(attn_kernel, cudaFuncAttributeMaxDynamicSharedMemorySize,
                         AT_SMEM_BYTES);
    cudaFuncSetAttribute(gemm_bf16x3, cudaFuncAttributeMaxDynamicSharedMemorySize,
                         G_SMEM_BYTES);

    const int N4 = MROWS * CDIM / 4;

    // 0) prepasses
    split_kernel<<<(N4 + 255) / 256, 256>>>(x, pxh, pxl, N4);
    transpose_split_kernel<<<dim3(QKV_COLS / 32, CDIM / 32), dim3(32, 8)>>>(
        w_qkv, pwqh, pwql, CDIM, QKV_COLS);
    transpose_split_kernel<<<dim3(CDIM / 32, CDIM / 32), dim3(32, 8)>>>(
        w_proj, pwph, pwpl, CDIM, CDIM);
    biasmask_kernel<<<(HEADS * SEQ * SEQ + 255) / 256, 256>>>(rel_table);

    // 1) QKV projection -> hi/lo bf16 output directly
    gemm_bf16x3<<<dim3(QKV_COLS / 128, MROWS / 128), 256, G_SMEM_BYTES>>>(
        pxh, pxl, pwqh, pwql, b_qkv, nullptr, pqh, pql, QKV_COLS);

    // 2) attention (bf16x3 tensor cores) -> hi/lo split output
    attn_kernel<<<dim3(SEQ / 64, HEADS, BATCH), 256, AT_SMEM_BYTES>>>();

    // 3) output projection -> fp32 out
    gemm_bf16x3<<<dim3(CDIM / 128, MROWS / 128), 256, G_SMEM_BYTES>>>(
        px2h, px2l, pwph, pwpl, b_proj, out, nullptr, nullptr, CDIM);
}

// round 7
// speedup vs baseline: 2.4595x; 1.1341x over previous
#include <cuda_runtime.h>
#include <cuda_bf16.h>
#include <cstdint>

// ---------------------------------------------------------------------------
// Problem dimensions (fixed by the reference)
// ---------------------------------------------------------------------------
#define BATCH     32
#define HEADS     12
#define SEQ       576
#define HD        64
#define CDIM      768
#define MROWS     (BATCH * SEQ)      // 18432
#define QKV_COLS  (3 * CDIM)         // 2304
#define GRID_SZ   24
#define MSIZE     47
#define MASK_D    12
#define SOFT_SCALE 0.125f

// ---------------------------------------------------------------------------
// Scratch (device globals)
// ---------------------------------------------------------------------------
__device__ float g_bm[(size_t)HEADS * SEQ * SEQ];                 // 16 MB
__device__ __nv_bfloat16 g_qkvh[(size_t)MROWS * QKV_COLS];
__device__ __nv_bfloat16 g_qkvl[(size_t)MROWS * QKV_COLS];
__device__ __nv_bfloat16 g_xh[(size_t)MROWS * CDIM];
__device__ __nv_bfloat16 g_xl[(size_t)MROWS * CDIM];
__device__ __nv_bfloat16 g_x2h[(size_t)MROWS * CDIM];
__device__ __nv_bfloat16 g_x2l[(size_t)MROWS * CDIM];
__device__ __nv_bfloat16 g_wqkvTh[(size_t)QKV_COLS * CDIM];
__device__ __nv_bfloat16 g_wqkvTl[(size_t)QKV_COLS * CDIM];
__device__ __nv_bfloat16 g_wprojTh[(size_t)CDIM * CDIM];
__device__ __nv_bfloat16 g_wprojTl[(size_t)CDIM * CDIM];

// ---------------------------------------------------------------------------
// Helpers
// ---------------------------------------------------------------------------
__device__ __forceinline__ void cp_async16(uint32_t smem_dst, const void* gptr) {
    asm volatile("cp.async.cg.shared.global [%0], [%1], 16;"
                 :: "r"(smem_dst), "l"(gptr));
}
__device__ __forceinline__ void cp_commit() { asm volatile("cp.async.commit_group;"); }
__device__ __forceinline__ void cp_wait0()  { asm volatile("cp.async.wait_group 0;"); }
__device__ __forceinline__ void cp_wait1()  { asm volatile("cp.async.wait_group 1;"); }

__device__ __forceinline__ void mma_bf16(
    float* c, uint32_t a0, uint32_t a1, uint32_t a2, uint32_t a3,
    uint32_t b0, uint32_t b1)
{
    asm volatile(
        "mma.sync.aligned.m16n8k16.row.col.f32.bf16.bf16.f32 "
        "{%0,%1,%2,%3}, {%4,%5,%6,%7}, {%8,%9}, {%0,%1,%2,%3};"
        : "+f"(c[0]), "+f"(c[1]), "+f"(c[2]), "+f"(c[3])
        : "r"(a0), "r"(a1), "r"(a2), "r"(a3), "r"(b0), "r"(b1));
}

__device__ __forceinline__ void ldsm_x4(uint32_t& r0, uint32_t& r1,
                                        uint32_t& r2, uint32_t& r3,
                                        uint32_t addr) {
    asm volatile("ldmatrix.sync.aligned.m8n8.x4.shared.b16 {%0,%1,%2,%3}, [%4];"
                 : "=r"(r0), "=r"(r1), "=r"(r2), "=r"(r3) : "r"(addr));
}
__device__ __forceinline__ void ldsm_x4_t(uint32_t& r0, uint32_t& r1,
                                          uint32_t& r2, uint32_t& r3,
                                          uint32_t addr) {
    asm volatile("ldmatrix.sync.aligned.m8n8.x4.trans.shared.b16 {%0,%1,%2,%3}, [%4];"
                 : "=r"(r0), "=r"(r1), "=r"(r2), "=r"(r3) : "r"(addr));
}

__device__ __forceinline__ void split_bf16(float v, __nv_bfloat16& h, __nv_bfloat16& l) {
    h = __float2bfloat16(v);
    l = __float2bfloat16(v - __bfloat162float(h));
}

// ---------------------------------------------------------------------------
// Prepass kernels
// ---------------------------------------------------------------------------
__global__ void split_kernel(const float* __restrict__ in,
                             __nv_bfloat16* __restrict__ hi,
                             __nv_bfloat16* __restrict__ lo, int n4) {
    int t = blockIdx.x * 256 + threadIdx.x;
    if (t >= n4) return;
    float4 v = *(const float4*)(in + (size_t)t * 4);
    __nv_bfloat16 h[4], l[4];
    split_bf16(v.x, h[0], l[0]);
    split_bf16(v.y, h[1], l[1]);
    split_bf16(v.z, h[2], l[2]);
    split_bf16(v.w, h[3], l[3]);
    *(ushort4*)(hi + (size_t)t * 4) = *(ushort4*)h;
    *(ushort4*)(lo + (size_t)t * 4) = *(ushort4*)l;
}

__global__ void transpose_split_kernel(const float* __restrict__ src,
                                       __nv_bfloat16* __restrict__ dstH,
                                       __nv_bfloat16* __restrict__ dstL,
                                       int R, int C) {
    __shared__ float t[32][33];
    int bx = blockIdx.x * 32, by = blockIdx.y * 32;
#pragma unroll
    for (int i = 0; i < 32; i += 8)
        t[threadIdx.y + i][threadIdx.x] =
            src[(size_t)(by + threadIdx.y + i) * C + bx + threadIdx.x];
    __syncthreads();
#pragma unroll
    for (int i = 0; i < 32; i += 8) {
        float v = t[threadIdx.x][threadIdx.y + i];
        __nv_bfloat16 h, l;
        split_bf16(v, h, l);
        size_t o = (size_t)(bx + threadIdx.y + i) * R + by + threadIdx.x;
        dstH[o] = h;
        dstL[o] = l;
    }
}

__global__ void biasmask_kernel(const float* __restrict__ rel_table) {
    int t = blockIdx.x * 256 + threadIdx.x;
    if (t >= HEADS * SEQ * SEQ) return;
    int h = t / (SEQ * SEQ);
    int r = t - h * (SEQ * SEQ);
    int q = r / SEQ;
    int k = r - q * SEQ;
    int qr = q / GRID_SZ, qc = q - qr * GRID_SZ;
    int kr = k / GRID_SZ, kc = k - kr * GRID_SZ;
    int dr = kr - qr, dc = kc - qc;
    int idx = (dr + GRID_SZ - 1) * MSIZE + (dc + GRID_SZ - 1);
    float v = rel_table[idx * HEADS + h];
    int cheb = max(abs(dr), abs(dc));
    if (cheb > MASK_D) v += -100.0f;
    g_bm[t] = v;
}

// ---------------------------------------------------------------------------
// bf16x3 tensor-core GEMM (ldmatrix inner loop)
// ---------------------------------------------------------------------------
#define KDIM 768
#define GBK  32
#define NST  (KDIM / GBK)
#define TROW 40
#define TILE_BYTES (128 * TROW * 2)
#define STAGE_BYTES (4 * TILE_BYTES)
#define G_SMEM_BYTES (2 * STAGE_BYTES)

__global__ __launch_bounds__(256, 2)
void gemm_bf16x3(const __nv_bfloat16* __restrict__ Ah,
                 const __nv_bfloat16* __restrict__ Al,
                 const __nv_bfloat16* __restrict__ Bh,
                 const __nv_bfloat16* __restrict__ Bl,
                 const float* __restrict__ bias,
                 float* __restrict__ Cf,
                 __nv_bfloat16* __restrict__ Ch,
                 __nv_bfloat16* __restrict__ Cl, int Nt) {
    extern __shared__ __nv_bfloat16 smb[];
    const uint32_t smem0 = (uint32_t)__cvta_generic_to_shared(smb);

    const int tid = threadIdx.x;
    const int wid = tid >> 5;
    const int lane = tid & 31;
    const int g = lane >> 2;
    const int tig = lane & 3;
    const int l8 = lane & 7;
    const int sel = lane >> 3;       // 0..3
    const int wm = wid & 1;
    const int wn = wid >> 1;
    const int tileM = blockIdx.y, tileN = blockIdx.x;

    const __nv_bfloat16* Abh = Ah + (size_t)tileM * 128 * KDIM;
    const __nv_bfloat16* Abl = Al + (size_t)tileM * 128 * KDIM;
    const __nv_bfloat16* Bbh = Bh + (size_t)tileN * 128 * KDIM;
    const __nv_bfloat16* Bbl = Bl + (size_t)tileN * 128 * KDIM;

    // ldmatrix base addresses (bytes)
    // A (row-major m16k16): row = wm*64 + (sel&1)*8 + l8, colbase = (sel>>1)*8
    const uint32_t aRC = (uint32_t)((wm * 64 + (sel & 1) * 8 + l8) * TROW + (sel >> 1) * 8) * 2;
    // B (pack 2 n8k16): row = wn*32 + (sel>>1)*8 + l8, colbase = (sel&1)*8
    const uint32_t bRC = (uint32_t)((wn * 32 + (sel >> 1) * 8 + l8) * TROW + (sel & 1) * 8) * 2;
    const uint32_t aAH = smem0 + 0 * TILE_BYTES + aRC;
    const uint32_t aAL = smem0 + 1 * TILE_BYTES + aRC;
    const uint32_t bAH = smem0 + 2 * TILE_BYTES + bRC;
    const uint32_t bAL = smem0 + 3 * TILE_BYTES + bRC;

    float acc[4][4][4];
#pragma unroll
    for (int i = 0; i < 4; i++)
#pragma unroll
        for (int j = 0; j < 4; j++)
#pragma unroll
            for (int r = 0; r < 4; r++) acc[i][j][r] = 0.0f;

    auto issue = [&](int s, int buf) {
        const int k0 = s * GBK;
        const uint32_t base = smem0 + buf * STAGE_BYTES;
#pragma unroll
        for (int rep = 0; rep < 2; rep++) {
            int c = tid + rep * 256;
            int row = c >> 2, ch = c & 3;
            uint32_t soff = (uint32_t)(row * TROW + ch * 8) * 2;
            size_t goff = (size_t)row * KDIM + k0 + ch * 8;
            cp_async16(base + 0 * TILE_BYTES + soff, Abh + goff);
            cp_async16(base + 1 * TILE_BYTES + soff, Abl + goff);
            cp_async16(base + 2 * TILE_BYTES + soff, Bbh + goff);
            cp_async16(base + 3 * TILE_BYTES + soff, Bbl + goff);
        }
        cp_commit();
    };

    issue(0, 0);

    int buf = 0;
    for (int s = 0; s < NST; s++) {
        cp_wait0();
        __syncthreads();
        if (s + 1 < NST) issue(s + 1, buf ^ 1);

        const uint32_t bo = (uint32_t)buf * STAGE_BYTES;
#pragma unroll
        for (int k16 = 0; k16 < 2; k16++) {
            const uint32_t kk2 = (uint32_t)(k16 * 16) * 2;
            uint32_t bh[4][2], bl[4][2];
#pragma unroll
            for (int jp = 0; jp < 2; jp++) {
                const uint32_t jo = (uint32_t)(jp * 16 * TROW) * 2 + kk2;
                uint32_t t0, t1, t2, t3;
                ldsm_x4(t0, t1, t2, t3, bAH + bo + jo);
                bh[2 * jp][0] = t0; bh[2 * jp][1] = t1;
                bh[2 * jp + 1][0] = t2; bh[2 * jp + 1][1] = t3;
                ldsm_x4(t0, t1, t2, t3, bAL + bo + jo);
                bl[2 * jp][0] = t0; bl[2 * jp][1] = t1;
                bl[2 * jp + 1][0] = t2; bl[2 * jp + 1][1] = t3;
            }
#pragma unroll
            for (int i = 0; i < 4; i++) {
                const uint32_t io = (uint32_t)(i * 16 * TROW) * 2 + kk2;
                uint32_t ah0, ah1, ah2, ah3, al0, al1, al2, al3;
                ldsm_x4(ah0, ah1, ah2, ah3, aAH + bo + io);
                ldsm_x4(al0, al1, al2, al3, aAL + bo + io);
#pragma unroll
                for (int j = 0; j < 4; j++) {
                    mma_bf16(acc[i][j], al0, al1, al2, al3, bh[j][0], bh[j][1]);
                    mma_bf16(acc[i][j], ah0, ah1, ah2, ah3, bl[j][0], bl[j][1]);
                    mma_bf16(acc[i][j], ah0, ah1, ah2, ah3, bh[j][0], bh[j][1]);
                }
            }
        }
        __syncthreads();
        buf ^= 1;
    }

#pragma unroll
    for (int i = 0; i < 4; i++) {
        const int row = tileM * 128 + wm * 64 + i * 16 + g;
#pragma unroll
        for (int j = 0; j < 4; j++) {
            const int col = tileN * 128 + wn * 32 + j * 8 + 2 * tig;
            const float b0 = bias[col], b1 = bias[col + 1];
            float v0 = acc[i][j][0] + b0, v1 = acc[i][j][1] + b1;
            float v2 = acc[i][j][2] + b0, v3 = acc[i][j][3] + b1;
            if (Cf) {
                *(float2*)(Cf + (size_t)row * Nt + col) = make_float2(v0, v1);
                *(float2*)(Cf + (size_t)(row + 8) * Nt + col) = make_float2(v2, v3);
            } else {
                __nv_bfloat16 h[2], l[2];
                split_bf16(v0, h[0], l[0]); split_bf16(v1, h[1], l[1]);
                *(ushort2*)(Ch + (size_t)row * Nt + col) = *(ushort2*)h;
                *(ushort2*)(Cl + (size_t)row * Nt + col) = *(ushort2*)l;
                split_bf16(v2, h[0], l[0]); split_bf16(v3, h[1], l[1]);
                *(ushort2*)(Ch + (size_t)(row + 8) * Nt + col) = *(ushort2*)h;
                *(ushort2*)(Cl + (size_t)(row + 8) * Nt + col) = *(ushort2*)l;
            }
        }
    }
}

// ---------------------------------------------------------------------------
// Flash attention, bf16x3, ldmatrix fragments, masked-tile skipping.
// ---------------------------------------------------------------------------
#define QK_STR 72
#define P_STR  72
#define SS_STR 65
#define NKT    (SEQ / 64)

#define OFF_QH  0
#define OFF_QL  (OFF_QH + 64 * QK_STR)
#define OFF_KH  (OFF_QL + 64 * QK_STR)
#define OFF_KL  (OFF_KH + 64 * QK_STR)
#define OFF_VH  (OFF_KL + 64 * QK_STR)
#define OFF_VL  (OFF_VH + 64 * QK_STR)
#define OFF_PH  (OFF_VL + 64 * QK_STR)
#define OFF_PL  (OFF_PH + 64 * P_STR)
#define OFF_F32 (OFF_PL + 64 * P_STR)
#define SS_F    0
#define MS_F    (SS_F + 64 * SS_STR)
#define LS_F    (MS_F + 64)
#define RS_F    (LS_F + 64)
#define RED_F   (RS_F + 64)
#define AT_SMEM_BYTES (OFF_F32 * 2 + (RED_F + 256) * 4)

__global__ __launch_bounds__(256, 2) void attn_kernel() {
    extern __shared__ __nv_bfloat16 smraw[];
    __nv_bfloat16* sPh = smraw + OFF_PH;
    __nv_bfloat16* sPl = smraw + OFF_PL;
    float* sS  = (float*)(smraw + OFF_F32) + SS_F;
    float* m_s = (float*)(smraw + OFF_F32) + MS_F;
    float* l_s = (float*)(smraw + OFF_F32) + LS_F;
    float* rsc = (float*)(smraw + OFF_F32) + RS_F;
    float* red = (float*)(smraw + OFF_F32) + RED_F;

    const uint32_t smemU = (uint32_t)__cvta_generic_to_shared(smraw);

    const int tid = threadIdx.x;
    const int wid = tid >> 5;
    const int lane = tid & 31;
    const int g = lane >> 2;
    const int tig = lane & 3;
    const int l8 = lane & 7;
    const int sel = lane >> 3;
    const int wm = wid & 3;
    const int wn = wid >> 2;
    const int m0 = wm * 16;
    const int n0 = wn * 32;

    const int qt = blockIdx.x, h = blockIdx.y, b = blockIdx.z;
    const int q0 = qt * 64;
    const int hoff = h * HD;
    const size_t rowBase = (size_t)b * SEQ;

    // active k-tile range (tiles fully masked by Chebyshev-row distance skipped)
    const int qlo = q0 / GRID_SZ, qhi = (q0 + 63) / GRID_SZ;
    int ktlo = 0, kthi = NKT - 1;
    while (ktlo < NKT && (64 * ktlo + 63) / GRID_SZ < qlo - MASK_D) ktlo++;
    while (kthi >= 0 && (64 * kthi) / GRID_SZ > qhi + MASK_D) kthi--;

    // ldmatrix base addresses
    const uint32_t qRC = (uint32_t)((m0 + (sel & 1) * 8 + l8) * QK_STR + (sel >> 1) * 8) * 2;
    const uint32_t kRC = (uint32_t)((n0 + (sel >> 1) * 8 + l8) * QK_STR + (sel & 1) * 8) * 2;
    const uint32_t pRC = (uint32_t)((m0 + (sel & 1) * 8 + l8) * P_STR + (sel >> 1) * 8) * 2;
    const uint32_t qAH = smemU + OFF_QH * 2 + qRC;
    const uint32_t qAL = smemU + OFF_QL * 2 + qRC;
    const uint32_t kAH = smemU + OFF_KH * 2 + kRC;
    const uint32_t kAL = smemU + OFF_KL * 2 + kRC;
    const uint32_t pAH = smemU + OFF_PH * 2 + pRC;
    const uint32_t pAL = smemU + OFF_PL * 2 + pRC;

    // ---- prologue: load Q (hi/lo) and K(ktlo)
    {
#pragma unroll
        for (int rep = 0; rep < 2; rep++) {
            int c = tid + rep * 256;
            int row = c >> 3, ch = c & 7;
            uint32_t soff = (uint32_t)(row * QK_STR + ch * 8) * 2;
            size_t gq = (rowBase + q0 + row) * QKV_COLS + hoff + ch * 8;
            size_t gk = (rowBase + ktlo * 64 + row) * QKV_COLS + CDIM + hoff + ch * 8;
            cp_async16(smemU + OFF_QH * 2 + soff, g_qkvh + gq);
            cp_async16(smemU + OFF_QL * 2 + soff, g_qkvl + gq);
            cp_async16(smemU + OFF_KH * 2 + soff, g_qkvh + gk);
            cp_async16(smemU + OFF_KL * 2 + soff, g_qkvl + gk);
        }
        cp_commit();
    }
    if (tid < 64) { m_s[tid] = -1e30f; l_s[tid] = 0.0f; }

    float accO[4][4];
#pragma unroll
    for (int j = 0; j < 4; j++)
#pragma unroll
        for (int r = 0; r < 4; r++) accO[j][r] = 0.0f;

    for (int kt = ktlo; kt <= kthi; kt++) {
        const int k0 = kt * 64;
        cp_wait0();
        __syncthreads();

        // ---- S = Q @ K^T (bf16x3, ldmatrix fragments)
        float sacc[4][4];
#pragma unroll
        for (int j = 0; j < 4; j++)
#pragma unroll
            for (int r = 0; r < 4; r++) sacc[j][r] = 0.0f;

#pragma unroll
        for (int kk4 = 0; kk4 < 4; kk4++) {
            const uint32_t kk2 = (uint32_t)(kk4 * 16) * 2;
            uint32_t qh0, qh1, qh2, qh3, ql0, ql1, ql2, ql3;
            ldsm_x4(qh0, qh1, qh2, qh3, qAH + kk2);
            ldsm_x4(ql0, ql1, ql2, ql3, qAL + kk2);
            uint32_t kh[4][2], kl[4][2];
#pragma unroll
            for (int jp = 0; jp < 2; jp++) {
                const uint32_t jo = (uint32_t)(jp * 16 * QK_STR) * 2 + kk2;
                uint32_t t0, t1, t2, t3;
                ldsm_x4(t0, t1, t2, t3, kAH + jo);
                kh[2 * jp][0] = t0; kh[2 * jp][1] = t1;
                kh[2 * jp + 1][0] = t2; kh[2 * jp + 1][1] = t3;
                ldsm_x4(t0, t1, t2, t3, kAL + jo);
                kl[2 * jp][0] = t0; kl[2 * jp][1] = t1;
                kl[2 * jp + 1][0] = t2; kl[2 * jp + 1][1] = t3;
            }
#pragma unroll
            for (int j = 0; j < 4; j++) {
                mma_bf16(sacc[j], ql0, ql1, ql2, ql3, kh[j][0], kh[j][1]);
                mma_bf16(sacc[j], qh0, qh1, qh2, qh3, kl[j][0], kl[j][1]);
                mma_bf16(sacc[j], qh0, qh1, qh2, qh3, kh[j][0], kh[j][1]);
            }
        }

        // ---- scores + bias/mask -> sS
        {
            const float* bmA = g_bm + ((size_t)h * SEQ + (q0 + m0 + g)) * SEQ + k0 + n0 + 2 * tig;
            const float* bmB = bmA + 8 * SEQ;
#pragma unroll
            for (int j = 0; j < 4; j++) {
                float2 ba = *(const float2*)(bmA + j * 8);
                float2 bb = *(const float2*)(bmB + j * 8);
                int c0 = n0 + j * 8 + 2 * tig;
                sS[(m0 + g) * SS_STR + c0]     = fmaf(sacc[j][0], SOFT_SCALE, ba.x);
                sS[(m0 + g) * SS_STR + c0 + 1] = fmaf(sacc[j][1], SOFT_SCALE, ba.y);
                sS[(m0 + 8 + g) * SS_STR + c0]     = fmaf(sacc[j][2], SOFT_SCALE, bb.x);
                sS[(m0 + 8 + g) * SS_STR + c0 + 1] = fmaf(sacc[j][3], SOFT_SCALE, bb.y);
            }
        }
        __syncthreads();

        // ---- prefetch V(kt) then K(kt+1)
        {
#pragma unroll
            for (int rep = 0; rep < 2; rep++) {
                int c = tid + rep * 256;
                int row = c >> 3, ch = c & 7;
                uint32_t soff = (uint32_t)(row * QK_STR + ch * 8) * 2;
                size_t gv = (rowBase + k0 + row) * QKV_COLS + 2 * CDIM + hoff + ch * 8;
                cp_async16(smemU + OFF_VH * 2 + soff, g_qkvh + gv);
                cp_async16(smemU + OFF_VL * 2 + soff, g_qkvl + gv);
            }
            cp_commit();
            if (kt < kthi) {
#pragma unroll
                for (int rep = 0; rep < 2; rep++) {
                    int c = tid + rep * 256;
                    int row = c >> 3, ch = c & 7;
                    uint32_t soff = (uint32_t)(row * QK_STR + ch * 8) * 2;
                    size_t gk = (rowBase + k0 + 64 + row) * QKV_COLS + CDIM + hoff + ch * 8;
                    cp_async16(smemU + OFF_KH * 2 + soff, g_qkvh + gk);
                    cp_async16(smemU + OFF_KL * 2 + soff, g_qkvl + gk);
                }
            }
            cp_commit();
        }

        // ---- softmax: row max
        {
            int r = tid & 63, seg = tid >> 6;
            const float* srow = sS + r * SS_STR + seg * 16;
            float pm = srow[0];
#pragma unroll
            for (int j = 1; j < 16; j++) pm = fmaxf(pm, srow[j]);
            red[seg * 64 + r] = pm;
        }
        __syncthreads();
        if (tid < 64) {
            int r = tid;
            float mn = fmaxf(fmaxf(red[r], red[64 + r]), fmaxf(red[128 + r], red[192 + r]));
            float mo = m_s[r];
            mn = fmaxf(mo, mn);
            m_s[r] = mn;
            rsc[r] = __expf(mo - mn);
        }
        __syncthreads();
        // ---- exp pass -> Ph/Pl split, partial sums
        {
            int r = tid & 63, seg = tid >> 6;
            float mr = m_s[r];
            const float* srow = sS + r * SS_STR + seg * 16;
            __nv_bfloat16* ph = sPh + r * P_STR + seg * 16;
            __nv_bfloat16* pl = sPl + r * P_STR + seg * 16;
            float ps = 0.0f;
#pragma unroll
            for (int j = 0; j < 16; j++) {
                float e = __expf(srow[j] - mr);
                __nv_bfloat16 eh, el;
                split_bf16(e, eh, el);
                ph[j] = eh;
                pl[j] = el;
                ps += e;
            }
            red[seg * 64 + r] = ps;
        }
        __syncthreads();
        if (tid < 64) {
            int r = tid;
            l_s[r] = l_s[r] * rsc[r] + (red[r] + red[64 + r]) + (red[128 + r] + red[192 + r]);
        }

        cp_wait1();
        __syncthreads();

        // ---- rescale O, then O += P @ V
        {
            float r0 = rsc[m0 + g], r1 = rsc[m0 + 8 + g];
#pragma unroll
            for (int j = 0; j < 4; j++) {
                accO[j][0] *= r0; accO[j][1] *= r0;
                accO[j][2] *= r1; accO[j][3] *= r1;
            }
        }
        {
            const int quad = lane >> 3, lrow = lane & 7;
            const int ksub = (quad & 1) * 8;
#pragma unroll
            for (int kk4 = 0; kk4 < 4; kk4++) {
                const int kk = kk4 * 16;
                uint32_t ph0, ph1, ph2, ph3, pl0, pl1, pl2, pl3;
                ldsm_x4(ph0, ph1, ph2, ph3, pAH + (uint32_t)kk * 2);
                ldsm_x4(pl0, pl1, pl2, pl3, pAL + (uint32_t)kk * 2);
#pragma unroll
                for (int jp = 0; jp < 2; jp++) {
                    const int jj = jp * 2 + (quad >> 1);
                    uint32_t vrow = (uint32_t)((kk + ksub + lrow) * QK_STR + n0 + jj * 8) * 2;
                    uint32_t vh0, vh1, vh2, vh3, vl0, vl1, vl2, vl3;
                    ldsm_x4_t(vh0, vh1, vh2, vh3, smemU + OFF_VH * 2 + vrow);
                    ldsm_x4_t(vl0, vl1, vl2, vl3, smemU + OFF_VL * 2 + vrow);
                    float* c0 = accO[jp * 2];
                    float* c1 = accO[jp * 2 + 1];
                    mma_bf16(c0, pl0, pl1, pl2, pl3, vh0, vh1);
                    mma_bf16(c0, ph0, ph1, ph2, ph3, vl0, vl1);
                    mma_bf16(c0, ph0, ph1, ph2, ph3, vh0, vh1);
                    mma_bf16(c1, pl0, pl1, pl2, pl3, vh2, vh3);
                    mma_bf16(c1, ph0, ph1, ph2, ph3, vl2, vl3);
                    mma_bf16(c1, ph0, ph1, ph2, ph3, vh2, vh3);
                }
            }
        }
    }

    // ---- normalize + hi/lo split store
    {
        float inv0 = 1.0f / l_s[m0 + g];
        float inv1 = 1.0f / l_s[m0 + 8 + g];
#pragma unroll
        for (int j = 0; j < 4; j++) {
            int col = hoff + n0 + j * 8 + 2 * tig;
            size_t o0 = (rowBase + q0 + m0 + g) * CDIM + col;
            size_t o1 = (rowBase + q0 + m0 + 8 + g) * CDIM + col;
            __nv_bfloat16 hh[2], ll[2];
            split_bf16(accO[j][0] * inv0, hh[0], ll[0]);
            split_bf16(accO[j][1] * inv0, hh[1], ll[1]);
            *(ushort2*)(g_x2h + o0) = *(ushort2*)hh;
            *(ushort2*)(g_x2l + o0) = *(ushort2*)ll;
            split_bf16(accO[j][2] * inv1, hh[0], ll[0]);
            split_bf16(accO[j][3] * inv1, hh[1], ll[1]);
            *(ushort2*)(g_x2h + o1) = *(ushort2*)hh;
            *(ushort2*)(g_x2l + o1) = *(ushort2*)ll;
        }
    }
}

// ---------------------------------------------------------------------------
// Launch
// ---------------------------------------------------------------------------
extern "C" void kernel_launch(void* const* d_in, const int* in_sizes, int n_in,
                              void* d_out, int out_size) {
    const float* x         = (const float*)d_in[0];
    const float* w_qkv     = (const float*)d_in[1];
    const float* b_qkv     = (const float*)d_in[2];
    const float* rel_table = (const float*)d_in[3];
    const float* w_proj    = (const float*)d_in[4];
    const float* b_proj    = (const float*)d_in[5];
    float* out = (float*)d_out;

    __nv_bfloat16 *pqh, *pql, *pxh, *pxl, *px2h, *px2l, *pwqh, *pwql, *pwph, *pwpl;
    cudaGetSymbolAddress((void**)&pqh, g_qkvh);
    cudaGetSymbolAddress((void**)&pql, g_qkvl);
    cudaGetSymbolAddress((void**)&pxh, g_xh);
    cudaGetSymbolAddress((void**)&pxl, g_xl);
    cudaGetSymbolAddress((void**)&px2h, g_x2h);
    cudaGetSymbolAddress((void**)&px2l, g_x2l);
    cudaGetSymbolAddress((void**)&pwqh, g_wqkvTh);
    cudaGetSymbolAddress((void**)&pwql, g_wqkvTl);
    cudaGetSymbolAddress((void**)&pwph, g_wprojTh);
    cudaGetSymbolAddress((void**)&pwpl, g_wprojTl);

    cudaFuncSetAttribute(attn_kernel, cudaFuncAttributeMaxDynamicSharedMemorySize,
                         AT_SMEM_BYTES);
    cudaFuncSetAttribute(gemm_bf16x3, cudaFuncAttributeMaxDynamicSharedMemorySize,
                         G_SMEM_BYTES);

    const int N4 = MROWS * CDIM / 4;

    // 0) prepasses
    split_kernel<<<(N4 + 255) / 256, 256>>>(x, pxh, pxl, N4);
    transpose_split_kernel<<<dim3(QKV_COLS / 32, CDIM / 32), dim3(32, 8)>>>(
        w_qkv, pwqh, pwql, CDIM, QKV_COLS);
    transpose_split_kernel<<<dim3(CDIM / 32, CDIM / 32), dim3(32, 8)>>>(
        w_proj, pwph, pwpl, CDIM, CDIM);
    biasmask_kernel<<<(HEADS * SEQ * SEQ + 255) / 256, 256>>>(rel_table);

    // 1) QKV projection -> hi/lo bf16 output
    gemm_bf16x3<<<dim3(QKV_COLS / 128, MROWS / 128), 256, G_SMEM_BYTES>>>(
        pxh, pxl, pwqh, pwql, b_qkv, nullptr, pqh, pql, QKV_COLS);

    // 2) attention -> hi/lo split output
    attn_kernel<<<dim3(SEQ / 64, HEADS, BATCH), 256, AT_SMEM_BYTES>>>();

    // 3) output projection -> fp32 out
    gemm_bf16x3<<<dim3(CDIM / 128, MROWS / 128), 256, G_SMEM_BYTES>>>(
        px2h, px2l, pwph, pwpl, b_proj, out, nullptr, nullptr, CDIM);
}

// round 9
// speedup vs baseline: 2.8115x; 1.1431x over previous
#include <cuda_runtime.h>
#include <cuda_bf16.h>
#include <cstdint>

// ---------------------------------------------------------------------------
// Problem dimensions (fixed by the reference)
// ---------------------------------------------------------------------------
#define BATCH     32
#define HEADS     12
#define SEQ       576
#define HD        64
#define CDIM      768
#define MROWS     (BATCH * SEQ)      // 18432
#define QKV_COLS  (3 * CDIM)         // 2304
#define GRID_SZ   24
#define MSIZE     47
#define MASK_D    12
#define SOFT_SCALE 0.125f

// ---------------------------------------------------------------------------
// Scratch (device globals)
// ---------------------------------------------------------------------------
__device__ float g_bm[(size_t)HEADS * SEQ * SEQ];                 // 16 MB
__device__ __nv_bfloat16 g_qkvh[(size_t)MROWS * QKV_COLS];
__device__ __nv_bfloat16 g_qkvl[(size_t)MROWS * QKV_COLS];
__device__ __nv_bfloat16 g_xh[(size_t)MROWS * CDIM];
__device__ __nv_bfloat16 g_xl[(size_t)MROWS * CDIM];
__device__ __nv_bfloat16 g_x2h[(size_t)MROWS * CDIM];
__device__ __nv_bfloat16 g_x2l[(size_t)MROWS * CDIM];
__device__ __nv_bfloat16 g_wqkvTh[(size_t)QKV_COLS * CDIM];
__device__ __nv_bfloat16 g_wqkvTl[(size_t)QKV_COLS * CDIM];
__device__ __nv_bfloat16 g_wprojTh[(size_t)CDIM * CDIM];
__device__ __nv_bfloat16 g_wprojTl[(size_t)CDIM * CDIM];

// ---------------------------------------------------------------------------
// Helpers
// ---------------------------------------------------------------------------
__device__ __forceinline__ void cp_async16(uint32_t smem_dst, const void* gptr) {
    asm volatile("cp.async.cg.shared.global [%0], [%1], 16;"
                 :: "r"(smem_dst), "l"(gptr));
}
__device__ __forceinline__ void cp_commit() { asm volatile("cp.async.commit_group;"); }
__device__ __forceinline__ void cp_wait0()  { asm volatile("cp.async.wait_group 0;"); }
__device__ __forceinline__ void cp_wait1()  { asm volatile("cp.async.wait_group 1;"); }

__device__ __forceinline__ void mma_bf16(
    float* c, uint32_t a0, uint32_t a1, uint32_t a2, uint32_t a3,
    uint32_t b0, uint32_t b1)
{
    asm volatile(
        "mma.sync.aligned.m16n8k16.row.col.f32.bf16.bf16.f32 "
        "{%0,%1,%2,%3}, {%4,%5,%6,%7}, {%8,%9}, {%0,%1,%2,%3};"
        : "+f"(c[0]), "+f"(c[1]), "+f"(c[2]), "+f"(c[3])
        : "r"(a0), "r"(a1), "r"(a2), "r"(a3), "r"(b0), "r"(b1));
}

__device__ __forceinline__ void ldsm_x4(uint32_t& r0, uint32_t& r1,
                                        uint32_t& r2, uint32_t& r3,
                                        uint32_t addr) {
    asm volatile("ldmatrix.sync.aligned.m8n8.x4.shared.b16 {%0,%1,%2,%3}, [%4];"
                 : "=r"(r0), "=r"(r1), "=r"(r2), "=r"(r3) : "r"(addr));
}
__device__ __forceinline__ void ldsm_x4_t(uint32_t& r0, uint32_t& r1,
                                          uint32_t& r2, uint32_t& r3,
                                          uint32_t addr) {
    asm volatile("ldmatrix.sync.aligned.m8n8.x4.trans.shared.b16 {%0,%1,%2,%3}, [%4];"
                 : "=r"(r0), "=r"(r1), "=r"(r2), "=r"(r3) : "r"(addr));
}

__device__ __forceinline__ void split_bf16(float v, __nv_bfloat16& h, __nv_bfloat16& l) {
    h = __float2bfloat16(v);
    l = __float2bfloat16(v - __bfloat162float(h));
}
// pack two floats as bf16x2 (a -> low, b -> high)
__device__ __forceinline__ uint32_t pack2(float a, float b) {
    __nv_bfloat162 t = __floats2bfloat162_rn(a, b);
    return *(uint32_t*)&t;
}

// ---------------------------------------------------------------------------
// Prepass kernels
// ---------------------------------------------------------------------------
__global__ void split_kernel(const float* __restrict__ in,
                             __nv_bfloat16* __restrict__ hi,
                             __nv_bfloat16* __restrict__ lo, int n4) {
    int t = blockIdx.x * 256 + threadIdx.x;
    if (t >= n4) return;
    float4 v = *(const float4*)(in + (size_t)t * 4);
    __nv_bfloat16 h[4], l[4];
    split_bf16(v.x, h[0], l[0]);
    split_bf16(v.y, h[1], l[1]);
    split_bf16(v.z, h[2], l[2]);
    split_bf16(v.w, h[3], l[3]);
    *(ushort4*)(hi + (size_t)t * 4) = *(ushort4*)h;
    *(ushort4*)(lo + (size_t)t * 4) = *(ushort4*)l;
}

__global__ void transpose_split_kernel(const float* __restrict__ src,
                                       __nv_bfloat16* __restrict__ dstH,
                                       __nv_bfloat16* __restrict__ dstL,
                                       int R, int C) {
    __shared__ float t[32][33];
    int bx = blockIdx.x * 32, by = blockIdx.y * 32;
#pragma unroll
    for (int i = 0; i < 32; i += 8)
        t[threadIdx.y + i][threadIdx.x] =
            src[(size_t)(by + threadIdx.y + i) * C + bx + threadIdx.x];
    __syncthreads();
#pragma unroll
    for (int i = 0; i < 32; i += 8) {
        float v = t[threadIdx.x][threadIdx.y + i];
        __nv_bfloat16 h, l;
        split_bf16(v, h, l);
        size_t o = (size_t)(bx + threadIdx.y + i) * R + by + threadIdx.x;
        dstH[o] = h;
        dstL[o] = l;
    }
}

__global__ void biasmask_kernel(const float* __restrict__ rel_table) {
    int t = blockIdx.x * 256 + threadIdx.x;
    if (t >= HEADS * SEQ * SEQ) return;
    int h = t / (SEQ * SEQ);
    int r = t - h * (SEQ * SEQ);
    int q = r / SEQ;
    int k = r - q * SEQ;
    int qr = q / GRID_SZ, qc = q - qr * GRID_SZ;
    int kr = k / GRID_SZ, kc = k - kr * GRID_SZ;
    int dr = kr - qr, dc = kc - qc;
    int idx = (dr + GRID_SZ - 1) * MSIZE + (dc + GRID_SZ - 1);
    float v = rel_table[idx * HEADS + h];
    int cheb = max(abs(dr), abs(dc));
    if (cheb > MASK_D) v += -100.0f;
    g_bm[t] = v;
}

// ---------------------------------------------------------------------------
// bf16x3 tensor-core GEMM (unchanged, verified)
// ---------------------------------------------------------------------------
#define KDIM 768
#define GBK  32
#define NST  (KDIM / GBK)
#define TROW 40
#define TILE_BYTES (128 * TROW * 2)
#define STAGE_BYTES (4 * TILE_BYTES)
#define G_SMEM_BYTES (2 * STAGE_BYTES)

__global__ __launch_bounds__(256, 2)
void gemm_bf16x3(const __nv_bfloat16* __restrict__ Ah,
                 const __nv_bfloat16* __restrict__ Al,
                 const __nv_bfloat16* __restrict__ Bh,
                 const __nv_bfloat16* __restrict__ Bl,
                 const float* __restrict__ bias,
                 float* __restrict__ Cf,
                 __nv_bfloat16* __restrict__ Ch,
                 __nv_bfloat16* __restrict__ Cl, int Nt) {
    extern __shared__ __nv_bfloat16 smb[];
    const uint32_t smem0 = (uint32_t)__cvta_generic_to_shared(smb);

    const int tid = threadIdx.x;
    const int wid = tid >> 5;
    const int lane = tid & 31;
    const int g = lane >> 2;
    const int tig = lane & 3;
    const int l8 = lane & 7;
    const int sel = lane >> 3;
    const int wm = wid & 1;
    const int wn = wid >> 1;
    const int tileM = blockIdx.y, tileN = blockIdx.x;

    const __nv_bfloat16* Abh = Ah + (size_t)tileM * 128 * KDIM;
    const __nv_bfloat16* Abl = Al + (size_t)tileM * 128 * KDIM;
    const __nv_bfloat16* Bbh = Bh + (size_t)tileN * 128 * KDIM;
    const __nv_bfloat16* Bbl = Bl + (size_t)tileN * 128 * KDIM;

    const uint32_t aRC = (uint32_t)((wm * 64 + (sel & 1) * 8 + l8) * TROW + (sel >> 1) * 8) * 2;
    const uint32_t bRC = (uint32_t)((wn * 32 + (sel >> 1) * 8 + l8) * TROW + (sel & 1) * 8) * 2;
    const uint32_t aAH = smem0 + 0 * TILE_BYTES + aRC;
    const uint32_t aAL = smem0 + 1 * TILE_BYTES + aRC;
    const uint32_t bAH = smem0 + 2 * TILE_BYTES + bRC;
    const uint32_t bAL = smem0 + 3 * TILE_BYTES + bRC;

    float acc[4][4][4];
#pragma unroll
    for (int i = 0; i < 4; i++)
#pragma unroll
        for (int j = 0; j < 4; j++)
#pragma unroll
            for (int r = 0; r < 4; r++) acc[i][j][r] = 0.0f;

    auto issue = [&](int s, int buf) {
        const int k0 = s * GBK;
        const uint32_t base = smem0 + buf * STAGE_BYTES;
#pragma unroll
        for (int rep = 0; rep < 2; rep++) {
            int c = tid + rep * 256;
            int row = c >> 2, ch = c & 3;
            uint32_t soff = (uint32_t)(row * TROW + ch * 8) * 2;
            size_t goff = (size_t)row * KDIM + k0 + ch * 8;
            cp_async16(base + 0 * TILE_BYTES + soff, Abh + goff);
            cp_async16(base + 1 * TILE_BYTES + soff, Abl + goff);
            cp_async16(base + 2 * TILE_BYTES + soff, Bbh + goff);
            cp_async16(base + 3 * TILE_BYTES + soff, Bbl + goff);
        }
        cp_commit();
    };

    issue(0, 0);

    int buf = 0;
    for (int s = 0; s < NST; s++) {
        cp_wait0();
        __syncthreads();
        if (s + 1 < NST) issue(s + 1, buf ^ 1);

        const uint32_t bo = (uint32_t)buf * STAGE_BYTES;
#pragma unroll
        for (int k16 = 0; k16 < 2; k16++) {
            const uint32_t kk2 = (uint32_t)(k16 * 16) * 2;
            uint32_t bh[4][2], bl[4][2];
#pragma unroll
            for (int jp = 0; jp < 2; jp++) {
                const uint32_t jo = (uint32_t)(jp * 16 * TROW) * 2 + kk2;
                uint32_t t0, t1, t2, t3;
                ldsm_x4(t0, t1, t2, t3, bAH + bo + jo);
                bh[2 * jp][0] = t0; bh[2 * jp][1] = t1;
                bh[2 * jp + 1][0] = t2; bh[2 * jp + 1][1] = t3;
                ldsm_x4(t0, t1, t2, t3, bAL + bo + jo);
                bl[2 * jp][0] = t0; bl[2 * jp][1] = t1;
                bl[2 * jp + 1][0] = t2; bl[2 * jp + 1][1] = t3;
            }
#pragma unroll
            for (int i = 0; i < 4; i++) {
                const uint32_t io = (uint32_t)(i * 16 * TROW) * 2 + kk2;
                uint32_t ah0, ah1, ah2, ah3, al0, al1, al2, al3;
                ldsm_x4(ah0, ah1, ah2, ah3, aAH + bo + io);
                ldsm_x4(al0, al1, al2, al3, aAL + bo + io);
#pragma unroll
                for (int j = 0; j < 4; j++) {
                    mma_bf16(acc[i][j], al0, al1, al2, al3, bh[j][0], bh[j][1]);
                    mma_bf16(acc[i][j], ah0, ah1, ah2, ah3, bl[j][0], bl[j][1]);
                    mma_bf16(acc[i][j], ah0, ah1, ah2, ah3, bh[j][0], bh[j][1]);
                }
            }
        }
        __syncthreads();
        buf ^= 1;
    }

#pragma unroll
    for (int i = 0; i < 4; i++) {
        const int row = tileM * 128 + wm * 64 + i * 16 + g;
#pragma unroll
        for (int j = 0; j < 4; j++) {
            const int col = tileN * 128 + wn * 32 + j * 8 + 2 * tig;
            const float b0 = bias[col], b1 = bias[col + 1];
            float v0 = acc[i][j][0] + b0, v1 = acc[i][j][1] + b1;
            float v2 = acc[i][j][2] + b0, v3 = acc[i][j][3] + b1;
            if (Cf) {
                *(float2*)(Cf + (size_t)row * Nt + col) = make_float2(v0, v1);
                *(float2*)(Cf + (size_t)(row + 8) * Nt + col) = make_float2(v2, v3);
            } else {
                __nv_bfloat16 h[2], l[2];
                split_bf16(v0, h[0], l[0]); split_bf16(v1, h[1], l[1]);
                *(ushort2*)(Ch + (size_t)row * Nt + col) = *(ushort2*)h;
                *(ushort2*)(Cl + (size_t)row * Nt + col) = *(ushort2*)l;
                split_bf16(v2, h[0], l[0]); split_bf16(v3, h[1], l[1]);
                *(ushort2*)(Ch + (size_t)(row + 8) * Nt + col) = *(ushort2*)h;
                *(ushort2*)(Cl + (size_t)(row + 8) * Nt + col) = *(ushort2*)l;
            }
        }
    }
}

// ---------------------------------------------------------------------------
// Flash attention, bf16x3, register-resident softmax + P fragments.
// 8 warps: wm=wid&3 (16 q-rows each), wn=wid>>2 (32-key slice of S/P).
// Each warp computes partial O over its key slice; wn halves summed at end.
// ---------------------------------------------------------------------------
#define QK_STR 72
#define NKT    (SEQ / 64)

#define OFF_QH  0
#define OFF_QL  (OFF_QH + 64 * QK_STR)
#define OFF_KH  (OFF_QL + 64 * QK_STR)
#define OFF_KL  (OFF_KH + 64 * QK_STR)
#define OFF_VH  (OFF_KL + 64 * QK_STR)
#define OFF_VL  (OFF_VH + 64 * QK_STR)
#define OFF_F32 (OFF_VL + 64 * QK_STR)    // 27648 bf16 -> fp32 region
#define ST_STR  66                         // EVEN stride: float2-safe staging
#define ST_F    0                          // 64*66 staging for O reduction
#define MS_F    (ST_F + 64 * ST_STR)
#define LS_F    (MS_F + 64)
#define RS_F    (LS_F + 64)
#define RED_F   (RS_F + 64)                // 128 floats
#define AT_SMEM_BYTES (OFF_F32 * 2 + (RED_F + 128) * 4)

__global__ __launch_bounds__(256, 2) void attn_kernel() {
    extern __shared__ __nv_bfloat16 smraw[];
    float* fb  = (float*)(smraw + OFF_F32);
    float* sSt = fb + ST_F;
    float* m_s = fb + MS_F;
    float* l_s = fb + LS_F;
    float* rsc = fb + RS_F;
    float* red = fb + RED_F;

    const uint32_t smemU = (uint32_t)__cvta_generic_to_shared(smraw);

    const int tid = threadIdx.x;
    const int wid = tid >> 5;
    const int lane = tid & 31;
    const int g = lane >> 2;
    const int tig = lane & 3;
    const int l8 = lane & 7;
    const int sel = lane >> 3;
    const int wm = wid & 3;
    const int wn = wid >> 2;
    const int m0 = wm * 16;
    const int n0 = wn * 32;

    const int qt = blockIdx.x, h = blockIdx.y, b = blockIdx.z;
    const int q0 = qt * 64;
    const int hoff = h * HD;
    const size_t rowBase = (size_t)b * SEQ;

    // active k-tile range
    const int qlo = q0 / GRID_SZ, qhi = (q0 + 63) / GRID_SZ;
    int ktlo = 0, kthi = NKT - 1;
    while (ktlo < NKT && (64 * ktlo + 63) / GRID_SZ < qlo - MASK_D) ktlo++;
    while (kthi >= 0 && (64 * kthi) / GRID_SZ > qhi + MASK_D) kthi--;

    // ldmatrix bases
    const uint32_t qRC = (uint32_t)((m0 + (sel & 1) * 8 + l8) * QK_STR + (sel >> 1) * 8) * 2;
    const uint32_t kRC = (uint32_t)((n0 + (sel >> 1) * 8 + l8) * QK_STR + (sel & 1) * 8) * 2;
    const uint32_t qAH = smemU + OFF_QH * 2 + qRC;
    const uint32_t qAL = smemU + OFF_QL * 2 + qRC;
    const uint32_t kAH = smemU + OFF_KH * 2 + kRC;
    const uint32_t kAL = smemU + OFF_KL * 2 + kRC;

    // ---- prologue: Q (hi/lo) and K(ktlo)
    {
#pragma unroll
        for (int rep = 0; rep < 2; rep++) {
            int c = tid + rep * 256;
            int row = c >> 3, ch = c & 7;
            uint32_t soff = (uint32_t)(row * QK_STR + ch * 8) * 2;
            size_t gq = (rowBase + q0 + row) * QKV_COLS + hoff + ch * 8;
            size_t gk = (rowBase + ktlo * 64 + row) * QKV_COLS + CDIM + hoff + ch * 8;
            cp_async16(smemU + OFF_QH * 2 + soff, g_qkvh + gq);
            cp_async16(smemU + OFF_QL * 2 + soff, g_qkvl + gq);
            cp_async16(smemU + OFF_KH * 2 + soff, g_qkvh + gk);
            cp_async16(smemU + OFF_KL * 2 + soff, g_qkvl + gk);
        }
        cp_commit();
    }
    if (tid < 64) { m_s[tid] = -1e30f; l_s[tid] = 0.0f; }

    float accO[8][4];
#pragma unroll
    for (int j = 0; j < 8; j++)
#pragma unroll
        for (int r = 0; r < 4; r++) accO[j][r] = 0.0f;

    for (int kt = ktlo; kt <= kthi; kt++) {
        const int k0 = kt * 64;
        cp_wait0();
        __syncthreads();

        // ---- prefetch bias/mask tile into registers (overlaps S-MMA)
        float2 bm0[4], bm1[4];
        {
            const float* bmA = g_bm + ((size_t)h * SEQ + (q0 + m0 + g)) * SEQ + k0 + n0 + 2 * tig;
            const float* bmB = bmA + 8 * SEQ;
#pragma unroll
            for (int j = 0; j < 4; j++) {
                bm0[j] = *(const float2*)(bmA + j * 8);
                bm1[j] = *(const float2*)(bmB + j * 8);
            }
        }

        // ---- S = Q @ K^T (bf16x3)
        float sacc[4][4];
#pragma unroll
        for (int j = 0; j < 4; j++)
#pragma unroll
            for (int r = 0; r < 4; r++) sacc[j][r] = 0.0f;

#pragma unroll
        for (int kk4 = 0; kk4 < 4; kk4++) {
            const uint32_t kk2 = (uint32_t)(kk4 * 16) * 2;
            uint32_t qh0, qh1, qh2, qh3, ql0, ql1, ql2, ql3;
            ldsm_x4(qh0, qh1, qh2, qh3, qAH + kk2);
            ldsm_x4(ql0, ql1, ql2, ql3, qAL + kk2);
            uint32_t kh[4][2], kl[4][2];
#pragma unroll
            for (int jp = 0; jp < 2; jp++) {
                const uint32_t jo = (uint32_t)(jp * 16 * QK_STR) * 2 + kk2;
                uint32_t t0, t1, t2, t3;
                ldsm_x4(t0, t1, t2, t3, kAH + jo);
                kh[2 * jp][0] = t0; kh[2 * jp][1] = t1;
                kh[2 * jp + 1][0] = t2; kh[2 * jp + 1][1] = t3;
                ldsm_x4(t0, t1, t2, t3, kAL + jo);
                kl[2 * jp][0] = t0; kl[2 * jp][1] = t1;
                kl[2 * jp + 1][0] = t2; kl[2 * jp + 1][1] = t3;
            }
#pragma unroll
            for (int j = 0; j < 4; j++) {
                mma_bf16(sacc[j], ql0, ql1, ql2, ql3, kh[j][0], kh[j][1]);
                mma_bf16(sacc[j], qh0, qh1, qh2, qh3, kl[j][0], kl[j][1]);
                mma_bf16(sacc[j], qh0, qh1, qh2, qh3, kh[j][0], kh[j][1]);
            }
        }

        // ---- scores in registers + per-thread row max
        float pm0 = -1e30f, pm1 = -1e30f;
#pragma unroll
        for (int j = 0; j < 4; j++) {
            sacc[j][0] = fmaf(sacc[j][0], SOFT_SCALE, bm0[j].x);
            sacc[j][1] = fmaf(sacc[j][1], SOFT_SCALE, bm0[j].y);
            sacc[j][2] = fmaf(sacc[j][2], SOFT_SCALE, bm1[j].x);
            sacc[j][3] = fmaf(sacc[j][3], SOFT_SCALE, bm1[j].y);
            pm0 = fmaxf(pm0, fmaxf(sacc[j][0], sacc[j][1]));
            pm1 = fmaxf(pm1, fmaxf(sacc[j][2], sacc[j][3]));
        }
        pm0 = fmaxf(pm0, __shfl_xor_sync(0xffffffffu, pm0, 1));
        pm0 = fmaxf(pm0, __shfl_xor_sync(0xffffffffu, pm0, 2));
        pm1 = fmaxf(pm1, __shfl_xor_sync(0xffffffffu, pm1, 1));
        pm1 = fmaxf(pm1, __shfl_xor_sync(0xffffffffu, pm1, 2));
        if (tig == 0) {
            red[wn * 64 + m0 + g] = pm0;
            red[wn * 64 + m0 + 8 + g] = pm1;
        }
        __syncthreads();   // red ready; also: all warps done reading K smem

        // ---- prefetch V(kt), then K(kt+1)
        {
#pragma unroll
            for (int rep = 0; rep < 2; rep++) {
                int c = tid + rep * 256;
                int row = c >> 3, ch = c & 7;
                uint32_t soff = (uint32_t)(row * QK_STR + ch * 8) * 2;
                size_t gv = (rowBase + k0 + row) * QKV_COLS + 2 * CDIM + hoff + ch * 8;
                cp_async16(smemU + OFF_VH * 2 + soff, g_qkvh + gv);
                cp_async16(smemU + OFF_VL * 2 + soff, g_qkvl + gv);
            }
            cp_commit();
            if (kt < kthi) {
#pragma unroll
                for (int rep = 0; rep < 2; rep++) {
                    int c = tid + rep * 256;
                    int row = c >> 3, ch = c & 7;
                    uint32_t soff = (uint32_t)(row * QK_STR + ch * 8) * 2;
                    size_t gk = (rowBase + k0 + 64 + row) * QKV_COLS + CDIM + hoff + ch * 8;
                    cp_async16(smemU + OFF_KH * 2 + soff, g_qkvh + gk);
                    cp_async16(smemU + OFF_KL * 2 + soff, g_qkvl + gk);
                }
            }
            cp_commit();
        }

        if (tid < 64) {
            int r = tid;
            float mn = fmaxf(m_s[r], fmaxf(red[r], red[64 + r]));
            rsc[r] = __expf(m_s[r] - mn);
            m_s[r] = mn;
        }
        __syncthreads();

        // ---- exp in registers -> P fragments (hi/lo), row sums
        uint32_t pa_h[2][4], pa_l[2][4];
        float ps0 = 0.0f, ps1 = 0.0f;
        {
            float mr0 = m_s[m0 + g];
            float mr1 = m_s[m0 + 8 + g];
#pragma unroll
            for (int j = 0; j < 4; j++) {
                float e0 = __expf(sacc[j][0] - mr0);
                float e1 = __expf(sacc[j][1] - mr0);
                float e2 = __expf(sacc[j][2] - mr1);
                float e3 = __expf(sacc[j][3] - mr1);
                ps0 += e0 + e1;
                ps1 += e2 + e3;
                float h0 = __bfloat162float(__float2bfloat16(e0));
                float h1 = __bfloat162float(__float2bfloat16(e1));
                float h2 = __bfloat162float(__float2bfloat16(e2));
                float h3 = __bfloat162float(__float2bfloat16(e3));
                const int c = j >> 1;
                const int hi2 = (j & 1) * 2;   // 0 -> a0/a1, 1 -> a2/a3
                pa_h[c][hi2]     = pack2(h0, h1);
                pa_h[c][hi2 + 1] = pack2(h2, h3);
                pa_l[c][hi2]     = pack2(e0 - h0, e1 - h1);
                pa_l[c][hi2 + 1] = pack2(e2 - h2, e3 - h3);
            }
        }
        ps0 += __shfl_xor_sync(0xffffffffu, ps0, 1);
        ps0 += __shfl_xor_sync(0xffffffffu, ps0, 2);
        ps1 += __shfl_xor_sync(0xffffffffu, ps1, 1);
        ps1 += __shfl_xor_sync(0xffffffffu, ps1, 2);
        if (tig == 0) {
            red[wn * 64 + m0 + g] = ps0;
            red[wn * 64 + m0 + 8 + g] = ps1;
        }
        __syncthreads();
        if (tid < 64) {
            int r = tid;
            l_s[r] = l_s[r] * rsc[r] + red[r] + red[64 + r];
        }

        cp_wait1();        // V ready
        __syncthreads();

        // ---- rescale O, then O += P @ V (warp's 32-key slice, all 64 d)
        {
            float r0 = rsc[m0 + g], r1 = rsc[m0 + 8 + g];
#pragma unroll
            for (int j = 0; j < 8; j++) {
                accO[j][0] *= r0; accO[j][1] *= r0;
                accO[j][2] *= r1; accO[j][3] *= r1;
            }
        }
        {
            const int quad = lane >> 3, lrow = lane & 7;
            const int ksub = (quad & 1) * 8;
            const int csel = (quad >> 1) * 8;
#pragma unroll
            for (int c = 0; c < 2; c++) {
                const int krow = n0 + c * 16 + ksub + lrow;
#pragma unroll
                for (int jp = 0; jp < 4; jp++) {
                    uint32_t vrow = (uint32_t)(krow * QK_STR + jp * 16 + csel) * 2;
                    uint32_t vh0, vh1, vh2, vh3, vl0, vl1, vl2, vl3;
                    ldsm_x4_t(vh0, vh1, vh2, vh3, smemU + OFF_VH * 2 + vrow);
                    ldsm_x4_t(vl0, vl1, vl2, vl3, smemU + OFF_VL * 2 + vrow);
                    float* c0 = accO[jp * 2];
                    float* c1 = accO[jp * 2 + 1];
                    mma_bf16(c0, pa_l[c][0], pa_l[c][1], pa_l[c][2], pa_l[c][3], vh0, vh1);
                    mma_bf16(c0, pa_h[c][0], pa_h[c][1], pa_h[c][2], pa_h[c][3], vl0, vl1);
                    mma_bf16(c0, pa_h[c][0], pa_h[c][1], pa_h[c][2], pa_h[c][3], vh0, vh1);
                    mma_bf16(c1, pa_l[c][0], pa_l[c][1], pa_l[c][2], pa_l[c][3], vh2, vh3);
                    mma_bf16(c1, pa_h[c][0], pa_h[c][1], pa_h[c][2], pa_h[c][3], vl2, vl3);
                    mma_bf16(c1, pa_h[c][0], pa_h[c][1], pa_h[c][2], pa_h[c][3], vh2, vh3);
                }
            }
        }
    }

    __syncthreads();       // l_s final; all PV done

    // ---- cross-warp (wn) reduction of partial O, normalize, split store
    if (wn == 1) {
#pragma unroll
        for (int j = 0; j < 8; j++) {
            *(float2*)(sSt + (m0 + g) * ST_STR + j * 8 + 2 * tig) =
                make_float2(accO[j][0], accO[j][1]);
            *(float2*)(sSt + (m0 + 8 + g) * ST_STR + j * 8 + 2 * tig) =
                make_float2(accO[j][2], accO[j][3]);
        }
    }
    __syncthreads();
    if (wn == 0) {
        float inv0 = 1.0f / l_s[m0 + g];
        float inv1 = 1.0f / l_s[m0 + 8 + g];
#pragma unroll
        for (int j = 0; j < 8; j++) {
            float2 o0 = *(const float2*)(sSt + (m0 + g) * ST_STR + j * 8 + 2 * tig);
            float2 o1 = *(const float2*)(sSt + (m0 + 8 + g) * ST_STR + j * 8 + 2 * tig);
            float v0 = (accO[j][0] + o0.x) * inv0;
            float v1 = (accO[j][1] + o0.y) * inv0;
            float v2 = (accO[j][2] + o1.x) * inv1;
            float v3 = (accO[j][3] + o1.y) * inv1;
            int col = hoff + j * 8 + 2 * tig;
            size_t a0 = (rowBase + q0 + m0 + g) * CDIM + col;
            size_t a1 = (rowBase + q0 + m0 + 8 + g) * CDIM + col;
            __nv_bfloat16 hh[2], ll[2];
            split_bf16(v0, hh[0], ll[0]); split_bf16(v1, hh[1], ll[1]);
            *(ushort2*)(g_x2h + a0) = *(ushort2*)hh;
            *(ushort2*)(g_x2l + a0) = *(ushort2*)ll;
            split_bf16(v2, hh[0], ll[0]); split_bf16(v3, hh[1], ll[1]);
            *(ushort2*)(g_x2h + a1) = *(ushort2*)hh;
            *(ushort2*)(g_x2l + a1) = *(ushort2*)ll;
        }
    }
}

// ---------------------------------------------------------------------------
// Launch (QKV GEMM at launch position 4 for ncu visibility)
// ---------------------------------------------------------------------------
extern "C" void kernel_launch(void* const* d_in, const int* in_sizes, int n_in,
                              void* d_out, int out_size) {
    const float* x         = (const float*)d_in[0];
    const float* w_qkv     = (const float*)d_in[1];
    const float* b_qkv     = (const float*)d_in[2];
    const float* rel_table = (const float*)d_in[3];
    const float* w_proj    = (const float*)d_in[4];
    const float* b_proj    = (const float*)d_in[5];
    float* out = (float*)d_out;

    __nv_bfloat16 *pqh, *pql, *pxh, *pxl, *px2h, *px2l, *pwqh, *pwql, *pwph, *pwpl;
    cudaGetSymbolAddress((void**)&pqh, g_qkvh);
    cudaGetSymbolAddress((void**)&pql, g_qkvl);
    cudaGetSymbolAddress((void**)&pxh, g_xh);
    cudaGetSymbolAddress((void**)&pxl, g_xl);
    cudaGetSymbolAddress((void**)&px2h, g_x2h);
    cudaGetSymbolAddress((void**)&px2l, g_x2l);
    cudaGetSymbolAddress((void**)&pwqh, g_wqkvTh);
    cudaGetSymbolAddress((void**)&pwql, g_wqkvTl);
    cudaGetSymbolAddress((void**)&pwph, g_wprojTh);
    cudaGetSymbolAddress((void**)&pwpl, g_wprojTl);

    cudaFuncSetAttribute(attn_kernel, cudaFuncAttributeMaxDynamicSharedMemorySize,
                         AT_SMEM_BYTES);
    cudaFuncSetAttribute(gemm_bf16x3, cudaFuncAttributeMaxDynamicSharedMemorySize,
                         G_SMEM_BYTES);

    const int N4 = MROWS * CDIM / 4;

    // 0) prepasses
    split_kernel<<<(N4 + 255) / 256, 256>>>(x, pxh, pxl, N4);
    transpose_split_kernel<<<dim3(QKV_COLS / 32, CDIM / 32), dim3(32, 8)>>>(
        w_qkv, pwqh, pwql, CDIM, QKV_COLS);
    transpose_split_kernel<<<dim3(CDIM / 32, CDIM / 32), dim3(32, 8)>>>(
        w_proj, pwph, pwpl, CDIM, CDIM);

    // 1) QKV projection -> hi/lo bf16 output   (launch #4)
    gemm_bf16x3<<<dim3(QKV_COLS / 128, MROWS / 128), 256, G_SMEM_BYTES>>>(
        pxh, pxl, pwqh, pwql, b_qkv, nullptr, pqh, pql, QKV_COLS);

    // 2) bias+mask precompute (independent of QKV; must precede attention)
    biasmask_kernel<<<(HEADS * SEQ * SEQ + 255) / 256, 256>>>(rel_table);

    // 3) attention -> hi/lo split output
    attn_kernel<<<dim3(SEQ / 64, HEADS, BATCH), 256, AT_SMEM_BYTES>>>();

    // 4) output projection -> fp32 out
    gemm_bf16x3<<<dim3(CDIM / 128, MROWS / 128), 256, G_SMEM_BYTES>>>(
        px2h, px2l, pwph, pwpl, b_proj, out, nullptr, nullptr, CDIM);
}

// round 10
// speedup vs baseline: 2.9156x; 1.0370x over previous
#include <cuda_runtime.h>
#include <cuda_bf16.h>
#include <cstdint>

// ---------------------------------------------------------------------------
// Problem dimensions (fixed by the reference)
// ---------------------------------------------------------------------------
#define BATCH     32
#define HEADS     12
#define SEQ       576
#define HD        64
#define CDIM      768
#define MROWS     (BATCH * SEQ)      // 18432
#define QKV_COLS  (3 * CDIM)         // 2304
#define GRID_SZ   24
#define MSIZE     47
#define MASK_D    12
#define SOFT_SCALE 0.125f

// ---------------------------------------------------------------------------
// Scratch (device globals)
// ---------------------------------------------------------------------------
__device__ float g_bm[(size_t)HEADS * SEQ * SEQ];                 // 16 MB
__device__ __nv_bfloat16 g_qkvh[(size_t)MROWS * QKV_COLS];
__device__ __nv_bfloat16 g_qkvl[(size_t)MROWS * QKV_COLS];
__device__ __nv_bfloat16 g_xh[(size_t)MROWS * CDIM];
__device__ __nv_bfloat16 g_xl[(size_t)MROWS * CDIM];
__device__ __nv_bfloat16 g_x2h[(size_t)MROWS * CDIM];
__device__ __nv_bfloat16 g_x2l[(size_t)MROWS * CDIM];
__device__ __nv_bfloat16 g_wqkvTh[(size_t)QKV_COLS * CDIM];
__device__ __nv_bfloat16 g_wqkvTl[(size_t)QKV_COLS * CDIM];
__device__ __nv_bfloat16 g_wprojTh[(size_t)CDIM * CDIM];
__device__ __nv_bfloat16 g_wprojTl[(size_t)CDIM * CDIM];

// ---------------------------------------------------------------------------
// Helpers
// ---------------------------------------------------------------------------
__device__ __forceinline__ void cp_async16(uint32_t smem_dst, const void* gptr) {
    asm volatile("cp.async.cg.shared.global [%0], [%1], 16;"
                 :: "r"(smem_dst), "l"(gptr));
}
__device__ __forceinline__ void cp_commit() { asm volatile("cp.async.commit_group;"); }
__device__ __forceinline__ void cp_wait0()  { asm volatile("cp.async.wait_group 0;"); }
__device__ __forceinline__ void cp_wait1()  { asm volatile("cp.async.wait_group 1;"); }

__device__ __forceinline__ void mma_bf16(
    float* c, uint32_t a0, uint32_t a1, uint32_t a2, uint32_t a3,
    uint32_t b0, uint32_t b1)
{
    asm volatile(
        "mma.sync.aligned.m16n8k16.row.col.f32.bf16.bf16.f32 "
        "{%0,%1,%2,%3}, {%4,%5,%6,%7}, {%8,%9}, {%0,%1,%2,%3};"
        : "+f"(c[0]), "+f"(c[1]), "+f"(c[2]), "+f"(c[3])
        : "r"(a0), "r"(a1), "r"(a2), "r"(a3), "r"(b0), "r"(b1));
}

__device__ __forceinline__ void ldsm_x4(uint32_t& r0, uint32_t& r1,
                                        uint32_t& r2, uint32_t& r3,
                                        uint32_t addr) {
    asm volatile("ldmatrix.sync.aligned.m8n8.x4.shared.b16 {%0,%1,%2,%3}, [%4];"
                 : "=r"(r0), "=r"(r1), "=r"(r2), "=r"(r3) : "r"(addr));
}
__device__ __forceinline__ void ldsm_x4_t(uint32_t& r0, uint32_t& r1,
                                          uint32_t& r2, uint32_t& r3,
                                          uint32_t addr) {
    asm volatile("ldmatrix.sync.aligned.m8n8.x4.trans.shared.b16 {%0,%1,%2,%3}, [%4];"
                 : "=r"(r0), "=r"(r1), "=r"(r2), "=r"(r3) : "r"(addr));
}

__device__ __forceinline__ void split_bf16(float v, __nv_bfloat16& h, __nv_bfloat16& l) {
    h = __float2bfloat16(v);
    l = __float2bfloat16(v - __bfloat162float(h));
}
__device__ __forceinline__ uint32_t pack2(float a, float b) {
    __nv_bfloat162 t = __floats2bfloat162_rn(a, b);
    return *(uint32_t*)&t;
}

// ---------------------------------------------------------------------------
// Prepass kernels
// ---------------------------------------------------------------------------
__global__ void split_kernel(const float* __restrict__ in,
                             __nv_bfloat16* __restrict__ hi,
                             __nv_bfloat16* __restrict__ lo, int n4) {
    int t = blockIdx.x * 256 + threadIdx.x;
    if (t >= n4) return;
    float4 v = *(const float4*)(in + (size_t)t * 4);
    __nv_bfloat16 h[4], l[4];
    split_bf16(v.x, h[0], l[0]);
    split_bf16(v.y, h[1], l[1]);
    split_bf16(v.z, h[2], l[2]);
    split_bf16(v.w, h[3], l[3]);
    *(ushort4*)(hi + (size_t)t * 4) = *(ushort4*)h;
    *(ushort4*)(lo + (size_t)t * 4) = *(ushort4*)l;
}

__global__ void transpose_split_kernel(const float* __restrict__ src,
                                       __nv_bfloat16* __restrict__ dstH,
                                       __nv_bfloat16* __restrict__ dstL,
                                       int R, int C) {
    __shared__ float t[32][33];
    int bx = blockIdx.x * 32, by = blockIdx.y * 32;
#pragma unroll
    for (int i = 0; i < 32; i += 8)
        t[threadIdx.y + i][threadIdx.x] =
            src[(size_t)(by + threadIdx.y + i) * C + bx + threadIdx.x];
    __syncthreads();
#pragma unroll
    for (int i = 0; i < 32; i += 8) {
        float v = t[threadIdx.x][threadIdx.y + i];
        __nv_bfloat16 h, l;
        split_bf16(v, h, l);
        size_t o = (size_t)(bx + threadIdx.y + i) * R + by + threadIdx.x;
        dstH[o] = h;
        dstL[o] = l;
    }
}

__global__ void biasmask_kernel(const float* __restrict__ rel_table) {
    int t = blockIdx.x * 256 + threadIdx.x;
    if (t >= HEADS * SEQ * SEQ) return;
    int h = t / (SEQ * SEQ);
    int r = t - h * (SEQ * SEQ);
    int q = r / SEQ;
    int k = r - q * SEQ;
    int qr = q / GRID_SZ, qc = q - qr * GRID_SZ;
    int kr = k / GRID_SZ, kc = k - kr * GRID_SZ;
    int dr = kr - qr, dc = kc - qc;
    int idx = (dr + GRID_SZ - 1) * MSIZE + (dc + GRID_SZ - 1);
    float v = rel_table[idx * HEADS + h];
    int cheb = max(abs(dr), abs(dc));
    if (cheb > MASK_D) v += -100.0f;
    g_bm[t] = v;
}

// ---------------------------------------------------------------------------
// bf16x3 tensor-core GEMM — dependency-spaced MMA passes, 1 sync/stage
// ---------------------------------------------------------------------------
#define KDIM 768
#define GBK  32
#define NST  (KDIM / GBK)
#define TROW 40
#define TILE_BYTES (128 * TROW * 2)
#define STAGE_BYTES (4 * TILE_BYTES)
#define G_SMEM_BYTES (2 * STAGE_BYTES)

__global__ __launch_bounds__(256, 2)
void gemm_bf16x3(const __nv_bfloat16* __restrict__ Ah,
                 const __nv_bfloat16* __restrict__ Al,
                 const __nv_bfloat16* __restrict__ Bh,
                 const __nv_bfloat16* __restrict__ Bl,
                 const float* __restrict__ bias,
                 float* __restrict__ Cf,
                 __nv_bfloat16* __restrict__ Ch,
                 __nv_bfloat16* __restrict__ Cl, int Nt) {
    extern __shared__ __nv_bfloat16 smb[];
    const uint32_t smem0 = (uint32_t)__cvta_generic_to_shared(smb);

    const int tid = threadIdx.x;
    const int wid = tid >> 5;
    const int lane = tid & 31;
    const int g = lane >> 2;
    const int tig = lane & 3;
    const int l8 = lane & 7;
    const int sel = lane >> 3;
    const int wm = wid & 1;
    const int wn = wid >> 1;
    const int tileM = blockIdx.y, tileN = blockIdx.x;

    const __nv_bfloat16* Abh = Ah + (size_t)tileM * 128 * KDIM;
    const __nv_bfloat16* Abl = Al + (size_t)tileM * 128 * KDIM;
    const __nv_bfloat16* Bbh = Bh + (size_t)tileN * 128 * KDIM;
    const __nv_bfloat16* Bbl = Bl + (size_t)tileN * 128 * KDIM;

    const uint32_t aRC = (uint32_t)((wm * 64 + (sel & 1) * 8 + l8) * TROW + (sel >> 1) * 8) * 2;
    const uint32_t bRC = (uint32_t)((wn * 32 + (sel >> 1) * 8 + l8) * TROW + (sel & 1) * 8) * 2;
    const uint32_t aAH = smem0 + 0 * TILE_BYTES + aRC;
    const uint32_t aAL = smem0 + 1 * TILE_BYTES + aRC;
    const uint32_t bAH = smem0 + 2 * TILE_BYTES + bRC;
    const uint32_t bAL = smem0 + 3 * TILE_BYTES + bRC;

    float acc[4][4][4];
#pragma unroll
    for (int i = 0; i < 4; i++)
#pragma unroll
        for (int j = 0; j < 4; j++)
#pragma unroll
            for (int r = 0; r < 4; r++) acc[i][j][r] = 0.0f;

    auto issue = [&](int s, int buf) {
        const int k0 = s * GBK;
        const uint32_t base = smem0 + buf * STAGE_BYTES;
#pragma unroll
        for (int rep = 0; rep < 2; rep++) {
            int c = tid + rep * 256;
            int row = c >> 2, ch = c & 3;
            uint32_t soff = (uint32_t)(row * TROW + ch * 8) * 2;
            size_t goff = (size_t)row * KDIM + k0 + ch * 8;
            cp_async16(base + 0 * TILE_BYTES + soff, Abh + goff);
            cp_async16(base + 1 * TILE_BYTES + soff, Abl + goff);
            cp_async16(base + 2 * TILE_BYTES + soff, Bbh + goff);
            cp_async16(base + 3 * TILE_BYTES + soff, Bbl + goff);
        }
        cp_commit();
    };

    issue(0, 0);

    int buf = 0;
    for (int s = 0; s < NST; s++) {
        cp_wait0();
        __syncthreads();    // stage data visible; prior-stage compute complete
        if (s + 1 < NST) issue(s + 1, buf ^ 1);

        const uint32_t bo = (uint32_t)buf * STAGE_BYTES;
#pragma unroll
        for (int k16 = 0; k16 < 2; k16++) {
            const uint32_t kk2 = (uint32_t)(k16 * 16) * 2;
            uint32_t bh[4][2], bl[4][2];
#pragma unroll
            for (int jp = 0; jp < 2; jp++) {
                const uint32_t jo = (uint32_t)(jp * 16 * TROW) * 2 + kk2;
                uint32_t t0, t1, t2, t3;
                ldsm_x4(t0, t1, t2, t3, bAH + jo + bo);
                bh[2 * jp][0] = t0; bh[2 * jp][1] = t1;
                bh[2 * jp + 1][0] = t2; bh[2 * jp + 1][1] = t3;
                ldsm_x4(t0, t1, t2, t3, bAL + jo + bo);
                bl[2 * jp][0] = t0; bl[2 * jp][1] = t1;
                bl[2 * jp + 1][0] = t2; bl[2 * jp + 1][1] = t3;
            }
            // process i in pairs; 3 separated passes -> acc deps spaced 8 MMAs
#pragma unroll
            for (int ip = 0; ip < 2; ip++) {
                uint32_t ah[2][4], al[2][4];
#pragma unroll
                for (int ii = 0; ii < 2; ii++) {
                    const uint32_t io = (uint32_t)((2 * ip + ii) * 16 * TROW) * 2 + kk2;
                    ldsm_x4(ah[ii][0], ah[ii][1], ah[ii][2], ah[ii][3], aAH + io + bo);
                    ldsm_x4(al[ii][0], al[ii][1], al[ii][2], al[ii][3], aAL + io + bo);
                }
#pragma unroll
                for (int ii = 0; ii < 2; ii++)
#pragma unroll
                    for (int j = 0; j < 4; j++)
                        mma_bf16(acc[2 * ip + ii][j],
                                 al[ii][0], al[ii][1], al[ii][2], al[ii][3],
                                 bh[j][0], bh[j][1]);
#pragma unroll
                for (int ii = 0; ii < 2; ii++)
#pragma unroll
                    for (int j = 0; j < 4; j++)
                        mma_bf16(acc[2 * ip + ii][j],
                                 ah[ii][0], ah[ii][1], ah[ii][2], ah[ii][3],
                                 bl[j][0], bl[j][1]);
#pragma unroll
                for (int ii = 0; ii < 2; ii++)
#pragma unroll
                    for (int j = 0; j < 4; j++)
                        mma_bf16(acc[2 * ip + ii][j],
                                 ah[ii][0], ah[ii][1], ah[ii][2], ah[ii][3],
                                 bh[j][0], bh[j][1]);
            }
        }
        buf ^= 1;
    }

#pragma unroll
    for (int i = 0; i < 4; i++) {
        const int row = tileM * 128 + wm * 64 + i * 16 + g;
#pragma unroll
        for (int j = 0; j < 4; j++) {
            const int col = tileN * 128 + wn * 32 + j * 8 + 2 * tig;
            const float b0 = bias[col], b1 = bias[col + 1];
            float v0 = acc[i][j][0] + b0, v1 = acc[i][j][1] + b1;
            float v2 = acc[i][j][2] + b0, v3 = acc[i][j][3] + b1;
            if (Cf) {
                *(float2*)(Cf + (size_t)row * Nt + col) = make_float2(v0, v1);
                *(float2*)(Cf + (size_t)(row + 8) * Nt + col) = make_float2(v2, v3);
            } else {
                __nv_bfloat16 h[2], l[2];
                split_bf16(v0, h[0], l[0]); split_bf16(v1, h[1], l[1]);
                *(ushort2*)(Ch + (size_t)row * Nt + col) = *(ushort2*)h;
                *(ushort2*)(Cl + (size_t)row * Nt + col) = *(ushort2*)l;
                split_bf16(v2, h[0], l[0]); split_bf16(v3, h[1], l[1]);
                *(ushort2*)(Ch + (size_t)(row + 8) * Nt + col) = *(ushort2*)h;
                *(ushort2*)(Cl + (size_t)(row + 8) * Nt + col) = *(ushort2*)l;
            }
        }
    }
}

// ---------------------------------------------------------------------------
// Flash attention, bf16x3, register softmax; dependency-spaced MMA passes.
// ---------------------------------------------------------------------------
#define QK_STR 72
#define NKT    (SEQ / 64)

#define OFF_QH  0
#define OFF_QL  (OFF_QH + 64 * QK_STR)
#define OFF_KH  (OFF_QL + 64 * QK_STR)
#define OFF_KL  (OFF_KH + 64 * QK_STR)
#define OFF_VH  (OFF_KL + 64 * QK_STR)
#define OFF_VL  (OFF_VH + 64 * QK_STR)
#define OFF_F32 (OFF_VL + 64 * QK_STR)
#define ST_STR  66
#define ST_F    0
#define MS_F    (ST_F + 64 * ST_STR)
#define LS_F    (MS_F + 64)
#define RS_F    (LS_F + 64)
#define RED_F   (RS_F + 64)
#define AT_SMEM_BYTES (OFF_F32 * 2 + (RED_F + 128) * 4)

__global__ __launch_bounds__(256, 2) void attn_kernel() {
    extern __shared__ __nv_bfloat16 smraw[];
    float* fb  = (float*)(smraw + OFF_F32);
    float* sSt = fb + ST_F;
    float* m_s = fb + MS_F;
    float* l_s = fb + LS_F;
    float* rsc = fb + RS_F;
    float* red = fb + RED_F;

    const uint32_t smemU = (uint32_t)__cvta_generic_to_shared(smraw);

    const int tid = threadIdx.x;
    const int wid = tid >> 5;
    const int lane = tid & 31;
    const int g = lane >> 2;
    const int tig = lane & 3;
    const int l8 = lane & 7;
    const int sel = lane >> 3;
    const int wm = wid & 3;
    const int wn = wid >> 2;
    const int m0 = wm * 16;
    const int n0 = wn * 32;

    const int qt = blockIdx.x, h = blockIdx.y, b = blockIdx.z;
    const int q0 = qt * 64;
    const int hoff = h * HD;
    const size_t rowBase = (size_t)b * SEQ;

    const int qlo = q0 / GRID_SZ, qhi = (q0 + 63) / GRID_SZ;
    int ktlo = 0, kthi = NKT - 1;
    while (ktlo < NKT && (64 * ktlo + 63) / GRID_SZ < qlo - MASK_D) ktlo++;
    while (kthi >= 0 && (64 * kthi) / GRID_SZ > qhi + MASK_D) kthi--;

    const uint32_t qRC = (uint32_t)((m0 + (sel & 1) * 8 + l8) * QK_STR + (sel >> 1) * 8) * 2;
    const uint32_t kRC = (uint32_t)((n0 + (sel >> 1) * 8 + l8) * QK_STR + (sel & 1) * 8) * 2;
    const uint32_t qAH = smemU + OFF_QH * 2 + qRC;
    const uint32_t qAL = smemU + OFF_QL * 2 + qRC;
    const uint32_t kAH = smemU + OFF_KH * 2 + kRC;
    const uint32_t kAL = smemU + OFF_KL * 2 + kRC;

    {
#pragma unroll
        for (int rep = 0; rep < 2; rep++) {
            int c = tid + rep * 256;
            int row = c >> 3, ch = c & 7;
            uint32_t soff = (uint32_t)(row * QK_STR + ch * 8) * 2;
            size_t gq = (rowBase + q0 + row) * QKV_COLS + hoff + ch * 8;
            size_t gk = (rowBase + ktlo * 64 + row) * QKV_COLS + CDIM + hoff + ch * 8;
            cp_async16(smemU + OFF_QH * 2 + soff, g_qkvh + gq);
            cp_async16(smemU + OFF_QL * 2 + soff, g_qkvl + gq);
            cp_async16(smemU + OFF_KH * 2 + soff, g_qkvh + gk);
            cp_async16(smemU + OFF_KL * 2 + soff, g_qkvl + gk);
        }
        cp_commit();
    }
    if (tid < 64) { m_s[tid] = -1e30f; l_s[tid] = 0.0f; }

    float accO[8][4];
#pragma unroll
    for (int j = 0; j < 8; j++)
#pragma unroll
        for (int r = 0; r < 4; r++) accO[j][r] = 0.0f;

    for (int kt = ktlo; kt <= kthi; kt++) {
        const int k0 = kt * 64;
        cp_wait0();
        __syncthreads();

        float2 bm0[4], bm1[4];
        {
            const float* bmA = g_bm + ((size_t)h * SEQ + (q0 + m0 + g)) * SEQ + k0 + n0 + 2 * tig;
            const float* bmB = bmA + 8 * SEQ;
#pragma unroll
            for (int j = 0; j < 4; j++) {
                bm0[j] = *(const float2*)(bmA + j * 8);
                bm1[j] = *(const float2*)(bmB + j * 8);
            }
        }

        // ---- S = Q @ K^T (bf16x3, pass-separated)
        float sacc[4][4];
#pragma unroll
        for (int j = 0; j < 4; j++)
#pragma unroll
            for (int r = 0; r < 4; r++) sacc[j][r] = 0.0f;

#pragma unroll
        for (int kk4 = 0; kk4 < 4; kk4++) {
            const uint32_t kk2 = (uint32_t)(kk4 * 16) * 2;
            uint32_t qh0, qh1, qh2, qh3, ql0, ql1, ql2, ql3;
            ldsm_x4(qh0, qh1, qh2, qh3, qAH + kk2);
            ldsm_x4(ql0, ql1, ql2, ql3, qAL + kk2);
            uint32_t kh[4][2], kl[4][2];
#pragma unroll
            for (int jp = 0; jp < 2; jp++) {
                const uint32_t jo = (uint32_t)(jp * 16 * QK_STR) * 2 + kk2;
                uint32_t t0, t1, t2, t3;
                ldsm_x4(t0, t1, t2, t3, kAH + jo);
                kh[2 * jp][0] = t0; kh[2 * jp][1] = t1;
                kh[2 * jp + 1][0] = t2; kh[2 * jp + 1][1] = t3;
                ldsm_x4(t0, t1, t2, t3, kAL + jo);
                kl[2 * jp][0] = t0; kl[2 * jp][1] = t1;
                kl[2 * jp + 1][0] = t2; kl[2 * jp + 1][1] = t3;
            }
#pragma unroll
            for (int j = 0; j < 4; j++)
                mma_bf16(sacc[j], ql0, ql1, ql2, ql3, kh[j][0], kh[j][1]);
#pragma unroll
            for (int j = 0; j < 4; j++)
                mma_bf16(sacc[j], qh0, qh1, qh2, qh3, kl[j][0], kl[j][1]);
#pragma unroll
            for (int j = 0; j < 4; j++)
                mma_bf16(sacc[j], qh0, qh1, qh2, qh3, kh[j][0], kh[j][1]);
        }

        // ---- scores + bias/mask + per-thread row max
        float pm0 = -1e30f, pm1 = -1e30f;
#pragma unroll
        for (int j = 0; j < 4; j++) {
            sacc[j][0] = fmaf(sacc[j][0], SOFT_SCALE, bm0[j].x);
            sacc[j][1] = fmaf(sacc[j][1], SOFT_SCALE, bm0[j].y);
            sacc[j][2] = fmaf(sacc[j][2], SOFT_SCALE, bm1[j].x);
            sacc[j][3] = fmaf(sacc[j][3], SOFT_SCALE, bm1[j].y);
            pm0 = fmaxf(pm0, fmaxf(sacc[j][0], sacc[j][1]));
            pm1 = fmaxf(pm1, fmaxf(sacc[j][2], sacc[j][3]));
        }
        pm0 = fmaxf(pm0, __shfl_xor_sync(0xffffffffu, pm0, 1));
        pm0 = fmaxf(pm0, __shfl_xor_sync(0xffffffffu, pm0, 2));
        pm1 = fmaxf(pm1, __shfl_xor_sync(0xffffffffu, pm1, 1));
        pm1 = fmaxf(pm1, __shfl_xor_sync(0xffffffffu, pm1, 2));
        if (tig == 0) {
            red[wn * 64 + m0 + g] = pm0;
            red[wn * 64 + m0 + 8 + g] = pm1;
        }
        __syncthreads();

        // ---- prefetch V(kt), then K(kt+1)
        {
#pragma unroll
            for (int rep = 0; rep < 2; rep++) {
                int c = tid + rep * 256;
                int row = c >> 3, ch = c & 7;
                uint32_t soff = (uint32_t)(row * QK_STR + ch * 8) * 2;
                size_t gv = (rowBase + k0 + row) * QKV_COLS + 2 * CDIM + hoff + ch * 8;
                cp_async16(smemU + OFF_VH * 2 + soff, g_qkvh + gv);
                cp_async16(smemU + OFF_VL * 2 + soff, g_qkvl + gv);
            }
            cp_commit();
            if (kt < kthi) {
#pragma unroll
                for (int rep = 0; rep < 2; rep++) {
                    int c = tid + rep * 256;
                    int row = c >> 3, ch = c & 7;
                    uint32_t soff = (uint32_t)(row * QK_STR + ch * 8) * 2;
                    size_t gk = (rowBase + k0 + 64 + row) * QKV_COLS + CDIM + hoff + ch * 8;
                    cp_async16(smemU + OFF_KH * 2 + soff, g_qkvh + gk);
                    cp_async16(smemU + OFF_KL * 2 + soff, g_qkvl + gk);
                }
            }
            cp_commit();
        }

        if (tid < 64) {
            int r = tid;
            float mn = fmaxf(m_s[r], fmaxf(red[r], red[64 + r]));
            rsc[r] = __expf(m_s[r] - mn);
            m_s[r] = mn;
        }
        __syncthreads();

        // ---- exp in registers -> P fragments (hi/lo), row sums
        uint32_t pa_h[2][4], pa_l[2][4];
        float ps0 = 0.0f, ps1 = 0.0f;
        {
            float mr0 = m_s[m0 + g];
            float mr1 = m_s[m0 + 8 + g];
#pragma unroll
            for (int j = 0; j < 4; j++) {
                float e0 = __expf(sacc[j][0] - mr0);
                float e1 = __expf(sacc[j][1] - mr0);
                float e2 = __expf(sacc[j][2] - mr1);
                float e3 = __expf(sacc[j][3] - mr1);
                ps0 += e0 + e1;
                ps1 += e2 + e3;
                float h0 = __bfloat162float(__float2bfloat16(e0));
                float h1 = __bfloat162float(__float2bfloat16(e1));
                float h2 = __bfloat162float(__float2bfloat16(e2));
                float h3 = __bfloat162float(__float2bfloat16(e3));
                const int c = j >> 1;
                const int hi2 = (j & 1) * 2;
                pa_h[c][hi2]     = pack2(h0, h1);
                pa_h[c][hi2 + 1] = pack2(h2, h3);
                pa_l[c][hi2]     = pack2(e0 - h0, e1 - h1);
                pa_l[c][hi2 + 1] = pack2(e2 - h2, e3 - h3);
            }
        }
        ps0 += __shfl_xor_sync(0xffffffffu, ps0, 1);
        ps0 += __shfl_xor_sync(0xffffffffu, ps0, 2);
        ps1 += __shfl_xor_sync(0xffffffffu, ps1, 1);
        ps1 += __shfl_xor_sync(0xffffffffu, ps1, 2);
        if (tig == 0) {
            red[wn * 64 + m0 + g] = ps0;
            red[wn * 64 + m0 + 8 + g] = ps1;
        }
        __syncthreads();
        if (tid < 64) {
            int r = tid;
            l_s[r] = l_s[r] * rsc[r] + red[r] + red[64 + r];
        }

        cp_wait1();
        __syncthreads();

        // ---- rescale O, then O += P @ V (V frags hoisted, 3 passes)
        {
            float r0 = rsc[m0 + g], r1 = rsc[m0 + 8 + g];
#pragma unroll
            for (int j = 0; j < 8; j++) {
                accO[j][0] *= r0; accO[j][1] *= r0;
                accO[j][2] *= r1; accO[j][3] *= r1;
            }
        }
        {
            const int quad = lane >> 3, lrow = lane & 7;
            const int ksub = (quad & 1) * 8;
            const int csel = (quad >> 1) * 8;
#pragma unroll
            for (int c = 0; c < 2; c++) {
                const int krow = n0 + c * 16 + ksub + lrow;
                uint32_t vh[4][4], vl[4][4];
#pragma unroll
                for (int jp = 0; jp < 4; jp++) {
                    uint32_t vrow = (uint32_t)(krow * QK_STR + jp * 16 + csel) * 2;
                    ldsm_x4_t(vh[jp][0], vh[jp][1], vh[jp][2], vh[jp][3],
                              smemU + OFF_VH * 2 + vrow);
                    ldsm_x4_t(vl[jp][0], vl[jp][1], vl[jp][2], vl[jp][3],
                              smemU + OFF_VL * 2 + vrow);
                }
#pragma unroll
                for (int jp = 0; jp < 4; jp++) {
                    mma_bf16(accO[jp * 2],     pa_l[c][0], pa_l[c][1], pa_l[c][2], pa_l[c][3],
                             vh[jp][0], vh[jp][1]);
                    mma_bf16(accO[jp * 2 + 1], pa_l[c][0], pa_l[c][1], pa_l[c][2], pa_l[c][3],
                             vh[jp][2], vh[jp][3]);
                }
#pragma unroll
                for (int jp = 0; jp < 4; jp++) {
                    mma_bf16(accO[jp * 2],     pa_h[c][0], pa_h[c][1], pa_h[c][2], pa_h[c][3],
                             vl[jp][0], vl[jp][1]);
                    mma_bf16(accO[jp * 2 + 1], pa_h[c][0], pa_h[c][1], pa_h[c][2], pa_h[c][3],
                             vl[jp][2], vl[jp][3]);
                }
#pragma unroll
                for (int jp = 0; jp < 4; jp++) {
                    mma_bf16(accO[jp * 2],     pa_h[c][0], pa_h[c][1], pa_h[c][2], pa_h[c][3],
                             vh[jp][0], vh[jp][1]);
                    mma_bf16(accO[jp * 2 + 1], pa_h[c][0], pa_h[c][1], pa_h[c][2], pa_h[c][3],
                             vh[jp][2], vh[jp][3]);
                }
            }
        }
    }

    __syncthreads();

    // ---- cross-warp (wn) reduction of partial O, normalize, split store
    if (wn == 1) {
#pragma unroll
        for (int j = 0; j < 8; j++) {
            *(float2*)(sSt + (m0 + g) * ST_STR + j * 8 + 2 * tig) =
                make_float2(accO[j][0], accO[j][1]);
            *(float2*)(sSt + (m0 + 8 + g) * ST_STR + j * 8 + 2 * tig) =
                make_float2(accO[j][2], accO[j][3]);
        }
    }
    __syncthreads();
    if (wn == 0) {
        float inv0 = 1.0f / l_s[m0 + g];
        float inv1 = 1.0f / l_s[m0 + 8 + g];
#pragma unroll
        for (int j = 0; j < 8; j++) {
            float2 o0 = *(const float2*)(sSt + (m0 + g) * ST_STR + j * 8 + 2 * tig);
            float2 o1 = *(const float2*)(sSt + (m0 + 8 + g) * ST_STR + j * 8 + 2 * tig);
            float v0 = (accO[j][0] + o0.x) * inv0;
            float v1 = (accO[j][1] + o0.y) * inv0;
            float v2 = (accO[j][2] + o1.x) * inv1;
            float v3 = (accO[j][3] + o1.y) * inv1;
            int col = hoff + j * 8 + 2 * tig;
            size_t a0 = (rowBase + q0 + m0 + g) * CDIM + col;
            size_t a1 = (rowBase + q0 + m0 + 8 + g) * CDIM + col;
            __nv_bfloat16 hh[2], ll[2];
            split_bf16(v0, hh[0], ll[0]); split_bf16(v1, hh[1], ll[1]);
            *(ushort2*)(g_x2h + a0) = *(ushort2*)hh;
            *(ushort2*)(g_x2l + a0) = *(ushort2*)ll;
            split_bf16(v2, hh[0], ll[0]); split_bf16(v3, hh[1], ll[1]);
            *(ushort2*)(g_x2h + a1) = *(ushort2*)hh;
            *(ushort2*)(g_x2l + a1) = *(ushort2*)ll;
        }
    }
}

// ---------------------------------------------------------------------------
// Launch
// ---------------------------------------------------------------------------
extern "C" void kernel_launch(void* const* d_in, const int* in_sizes, int n_in,
                              void* d_out, int out_size) {
    const float* x         = (const float*)d_in[0];
    const float* w_qkv     = (const float*)d_in[1];
    const float* b_qkv     = (const float*)d_in[2];
    const float* rel_table = (const float*)d_in[3];
    const float* w_proj    = (const float*)d_in[4];
    const float* b_proj    = (const float*)d_in[5];
    float* out = (float*)d_out;

    __nv_bfloat16 *pqh, *pql, *pxh, *pxl, *px2h, *px2l, *pwqh, *pwql, *pwph, *pwpl;
    cudaGetSymbolAddress((void**)&pqh, g_qkvh);
    cudaGetSymbolAddress((void**)&pql, g_qkvl);
    cudaGetSymbolAddress((void**)&pxh, g_xh);
    cudaGetSymbolAddress((void**)&pxl, g_xl);
    cudaGetSymbolAddress((void**)&px2h, g_x2h);
    cudaGetSymbolAddress((void**)&px2l, g_x2l);
    cudaGetSymbolAddress((void**)&pwqh, g_wqkvTh);
    cudaGetSymbolAddress((void**)&pwql, g_wqkvTl);
    cudaGetSymbolAddress((void**)&pwph, g_wprojTh);
    cudaGetSymbolAddress((void**)&pwpl, g_wprojTl);

    cudaFuncSetAttribute(attn_kernel, cudaFuncAttributeMaxDynamicSharedMemorySize,
                         AT_SMEM_BYTES);
    cudaFuncSetAttribute(gemm_bf16x3, cudaFuncAttributeMaxDynamicSharedMemorySize,
                         G_SMEM_BYTES);

    const int N4 = MROWS * CDIM / 4;

    // 0) prepasses
    split_kernel<<<(N4 + 255) / 256, 256>>>(x, pxh, pxl, N4);
    transpose_split_kernel<<<dim3(QKV_COLS / 32, CDIM / 32), dim3(32, 8)>>>(
        w_qkv, pwqh, pwql, CDIM, QKV_COLS);
    transpose_split_kernel<<<dim3(CDIM / 32, CDIM / 32), dim3(32, 8)>>>(
        w_proj, pwph, pwpl, CDIM, CDIM);

    // 1) QKV projection -> hi/lo bf16 output   (launch #4: ncu target)
    gemm_bf16x3<<<dim3(QKV_COLS / 128, MROWS / 128), 256, G_SMEM_BYTES>>>(
        pxh, pxl, pwqh, pwql, b_qkv, nullptr, pqh, pql, QKV_COLS);

    // 2) bias+mask precompute
    biasmask_kernel<<<(HEADS * SEQ * SEQ + 255) / 256, 256>>>(rel_table);

    // 3) attention -> hi/lo split output
    attn_kernel<<<dim3(SEQ / 64, HEADS, BATCH), 256, AT_SMEM_BYTES>>>();

    // 4) output projection -> fp32 out
    gemm_bf16x3<<<dim3(CDIM / 128, MROWS / 128), 256, G_SMEM_BYTES>>>(
        px2h, px2l, pwph, pwpl, b_proj, out, nullptr, nullptr, CDIM);
}